// round 15
// baseline (speedup 1.0000x reference)
#include <cuda_runtime.h>
#include <cuda_bf16.h>
#include <cuda_fp16.h>
#include <math.h>
#include <stdint.h>

// ---------------- constants ----------------
#define T_TOK   1024
#define D_MODEL 256
#define SEQ     512
#define NHEAD   4
#define DHEAD   64
#define NBASIS  32
#define RRANK   64
#define NNEUR   64
#define TOPK    8
#define DFF     1024
#define NLAYER  4
#define VOCAB   32000
#define TPB_A   32
#define RG_A    8
#define RPER_A  (RRANK / RG_A)
#define TPB_B   32
#define RG_B    4
#define RPER_B  (RRANK / RG_B)
#define NA_SZ   (NNEUR * 8192)
#define NB_SZ   (NNEUR * 16384)

// ---------------- scratch ----------------
__device__ float g_x[T_TOK * D_MODEL];
__device__ float g_nrm1[T_TOK * D_MODEL];
__device__ float g_q[T_TOK * D_MODEL];
__device__ float g_k[T_TOK * D_MODEL];
__device__ float g_v[T_TOK * D_MODEL];
__device__ float g_ctx[T_TOK * D_MODEL];
__device__ float g_query[T_TOK * D_MODEL];
__device__ float g_ffn[T_TOK * DFF];
__device__ float g_Rsoft[NLAYER * NNEUR * NBASIS];
__device__ float g_nemb[NLAYER * NNEUR * D_MODEL];
__device__ float g_hpart[RG_A * T_TOK * 64];
__device__ float g_ffnpart[RG_B * T_TOK * DFF];
__device__ float g_wdpart[2 * T_TOK * D_MODEL];
__device__ int   g_topi[T_TOK * TOPK];
__device__ float g_topw[T_TOK * TOPK];
__device__ __half g_NA1[NLAYER * NA_SZ];
__device__ __half g_NA2[NLAYER * NA_SZ];
__device__ __half g_NB1[NLAYER * NB_SZ];
__device__ __half g_NB2[NLAYER * NB_SZ];
__device__ uint32_t g_qW32[NLAYER * 65536];
__device__ uint32_t g_kW32[NLAYER * 65536];
__device__ uint32_t g_vW32[NLAYER * 65536];
__device__ uint32_t g_sW32[NLAYER * 131072];
__device__ uint32_t g_wdW32[NLAYER * 262144];

// ---------------- tf32 helpers ----------------
__device__ __forceinline__ uint32_t f2tf32(float f) {
    uint32_t u;
    asm("cvt.rna.tf32.f32 %0, %1;" : "=r"(u) : "f"(f));
    return u;
}
__device__ __forceinline__ void mma_tf32(float& c0, float& c1, float& c2, float& c3,
                                         uint32_t a0, uint32_t a1, uint32_t a2, uint32_t a3,
                                         uint32_t b0, uint32_t b1) {
    asm("mma.sync.aligned.m16n8k8.row.col.f32.tf32.tf32.f32 "
        "{%0,%1,%2,%3},{%4,%5,%6,%7},{%8,%9},{%0,%1,%2,%3};"
        : "+f"(c0), "+f"(c1), "+f"(c2), "+f"(c3)
        : "r"(a0), "r"(a1), "r"(a2), "r"(a3), "r"(b0), "r"(b1));
}
__device__ __forceinline__ void h8_to_f8(uint4 p, float* dst) {
    const __half2* h = (const __half2*)&p;
#pragma unroll
    for (int i = 0; i < 4; i++) {
        float2 f = __half22float2(h[i]);
        dst[2 * i] = f.x; dst[2 * i + 1] = f.y;
    }
}

// ---------------- merged upfront conversion ----------------
struct Cvt5 { const float* src[5]; uint32_t* dst[5]; int n[5]; };
__global__ void cvt5_kernel(Cvt5 j) {
    int a = blockIdx.y;
    int i = blockIdx.x * 256 + threadIdx.x;
    if (i < j.n[a]) j.dst[a][i] = f2tf32(j.src[a][i]);
}

// ---------------- embed ----------------
__global__ void embed_kernel(const int* __restrict__ ids, const float* __restrict__ te,
                             const float* __restrict__ pe, float* __restrict__ x) {
    int t = blockIdx.x, d = threadIdx.x;
    int s = t & (SEQ - 1);
    x[t * 256 + d] = te[ids[t] * 256 + d] + pe[s * 256 + d];
}

// ---------------- layernorm: warp per token ----------------
__global__ void ln_kernel(const float* __restrict__ x, const float* __restrict__ g,
                          const float* __restrict__ b, float* __restrict__ out) {
    int warp = threadIdx.x >> 5, lane = threadIdx.x & 31;
    int t = blockIdx.x * 8 + warp;
    float vals[8];
    float s = 0.f, s2 = 0.f;
#pragma unroll
    for (int qd = 0; qd < 8; qd++) {
        float v = x[t * 256 + lane + 32 * qd];
        vals[qd] = v; s += v; s2 = fmaf(v, v, s2);
    }
#pragma unroll
    for (int o = 16; o; o >>= 1) {
        s += __shfl_xor_sync(0xffffffffu, s, o);
        s2 += __shfl_xor_sync(0xffffffffu, s2, o);
    }
    float mean = s * (1.f / 256.f);
    float var = s2 * (1.f / 256.f) - mean * mean;
    float inv = rsqrtf(var + 1e-5f);
#pragma unroll
    for (int qd = 0; qd < 8; qd++) {
        int d = lane + 32 * qd;
        out[t * 256 + d] = (vals[qd] - mean) * inv * g[d] + b[d];
    }
}

// ---------------- split-K tf32 GEMM (reg-prefetch), partial out ----------------
__global__ __launch_bounds__(256) void tc_gemm_sk(const float* __restrict__ A,
                                                  const uint32_t* __restrict__ B,
                                                  float* __restrict__ Cpart,
                                                  int N, int K, int klen) {
    __shared__ uint32_t As[32 * 68];
    __shared__ uint32_t Bs[32 * 68];
    int tid = threadIdx.x, lane = tid & 31, wid = tid >> 5;
    int wm = (wid & 3) * 16, wn = (wid >> 2) * 32;
    int m0 = blockIdx.y * 64, n0 = blockIdx.x * 64;
    int gid = lane >> 2, tig = lane & 3;
    int kbeg = blockIdx.z * klen;
    float* C = Cpart + (size_t)blockIdx.z * T_TOK * D_MODEL;
    int arow[2], akq[2], bkb[2], bnq[2];
#pragma unroll
    for (int it = 0; it < 2; it++) {
        int u = tid + it * 256;
        arow[it] = u >> 3; akq[it] = (u & 7) * 4;
        bkb[it] = u >> 4; bnq[it] = (u & 15) * 4;
    }
    float4 aP[2]; uint4 bP[2];
#pragma unroll
    for (int it = 0; it < 2; it++) {
        aP[it] = *(const float4*)&A[(size_t)(m0 + arow[it]) * K + kbeg + akq[it]];
        bP[it] = *(const uint4*)&B[(size_t)(kbeg + bkb[it]) * N + n0 + bnq[it]];
    }
    float acc[4][4];
#pragma unroll
    for (int j = 0; j < 4; j++)
#pragma unroll
        for (int i = 0; i < 4; i++) acc[j][i] = 0.f;

    for (int k0 = kbeg; k0 < kbeg + klen; k0 += 32) {
#pragma unroll
        for (int it = 0; it < 2; it++) {
            As[(akq[it] + 0) * 68 + arow[it]] = f2tf32(aP[it].x);
            As[(akq[it] + 1) * 68 + arow[it]] = f2tf32(aP[it].y);
            As[(akq[it] + 2) * 68 + arow[it]] = f2tf32(aP[it].z);
            As[(akq[it] + 3) * 68 + arow[it]] = f2tf32(aP[it].w);
            *(uint4*)&Bs[bkb[it] * 68 + bnq[it]] = bP[it];
        }
        __syncthreads();
        if (k0 + 32 < kbeg + klen) {
#pragma unroll
            for (int it = 0; it < 2; it++) {
                aP[it] = *(const float4*)&A[(size_t)(m0 + arow[it]) * K + k0 + 32 + akq[it]];
                bP[it] = *(const uint4*)&B[(size_t)(k0 + 32 + bkb[it]) * N + n0 + bnq[it]];
            }
        }
#pragma unroll
        for (int s = 0; s < 4; s++) {
            int k = s * 8;
            uint32_t a0 = As[(k + tig) * 68 + wm + gid];
            uint32_t a1 = As[(k + tig) * 68 + wm + gid + 8];
            uint32_t a2 = As[(k + 4 + tig) * 68 + wm + gid];
            uint32_t a3 = As[(k + 4 + tig) * 68 + wm + gid + 8];
#pragma unroll
            for (int j = 0; j < 4; j++) {
                uint32_t b0 = Bs[(k + tig) * 68 + wn + j * 8 + gid];
                uint32_t b1 = Bs[(k + 4 + tig) * 68 + wn + j * 8 + gid];
                mma_tf32(acc[j][0], acc[j][1], acc[j][2], acc[j][3], a0, a1, a2, a3, b0, b1);
            }
        }
        __syncthreads();
    }
#pragma unroll
    for (int j = 0; j < 4; j++) {
        int n = n0 + wn + j * 8 + tig * 2;
        int m = m0 + wm + gid;
        size_t o0 = (size_t)m * N + n, o1 = (size_t)(m + 8) * N + n;
        C[o0] = acc[j][0]; C[o0 + 1] = acc[j][1]; C[o1] = acc[j][2]; C[o1 + 1] = acc[j][3];
    }
}

// combine: x += p0 + p1 + bias
__global__ void wdadd_kernel(const float* __restrict__ p, const float* __restrict__ bias,
                             float* __restrict__ x) {
    int idx = blockIdx.x * 256 + threadIdx.x;
    x[idx] += p[idx] + p[T_TOK * D_MODEL + idx] + bias[idx & 255];
}

// ---------------- batched tf32 GEMM (reg-prefetch, 4 weights) ----------------
struct W4u { const uint32_t* W[4]; const float* bias[4]; float* out[4]; };

__global__ __launch_bounds__(256) void tc_gemmb(const float* __restrict__ A, W4u gb,
                                                int M, int N, int K) {
    const uint32_t* __restrict__ B = gb.W[blockIdx.z];
    const float* __restrict__ bias = gb.bias[blockIdx.z];
    float* __restrict__ C = gb.out[blockIdx.z];
    __shared__ uint32_t As[32 * 68];
    __shared__ uint32_t Bs[32 * 68];
    int tid = threadIdx.x, lane = tid & 31, wid = tid >> 5;
    int wm = (wid & 3) * 16, wn = (wid >> 2) * 32;
    int m0 = blockIdx.y * 64, n0 = blockIdx.x * 64;
    int gid = lane >> 2, tig = lane & 3;
    int arow[2], akq[2], bkb[2], bnq[2];
#pragma unroll
    for (int it = 0; it < 2; it++) {
        int u = tid + it * 256;
        arow[it] = u >> 3; akq[it] = (u & 7) * 4;
        bkb[it] = u >> 4; bnq[it] = (u & 15) * 4;
    }
    float4 aP[2]; uint4 bP[2];
#pragma unroll
    for (int it = 0; it < 2; it++) {
        aP[it] = *(const float4*)&A[(size_t)(m0 + arow[it]) * K + akq[it]];
        bP[it] = *(const uint4*)&B[(size_t)bkb[it] * N + n0 + bnq[it]];
    }
    float acc[4][4];
#pragma unroll
    for (int j = 0; j < 4; j++)
#pragma unroll
        for (int i = 0; i < 4; i++) acc[j][i] = 0.f;

    for (int k0 = 0; k0 < K; k0 += 32) {
#pragma unroll
        for (int it = 0; it < 2; it++) {
            As[(akq[it] + 0) * 68 + arow[it]] = f2tf32(aP[it].x);
            As[(akq[it] + 1) * 68 + arow[it]] = f2tf32(aP[it].y);
            As[(akq[it] + 2) * 68 + arow[it]] = f2tf32(aP[it].z);
            As[(akq[it] + 3) * 68 + arow[it]] = f2tf32(aP[it].w);
            *(uint4*)&Bs[bkb[it] * 68 + bnq[it]] = bP[it];
        }
        __syncthreads();
        if (k0 + 32 < K) {
#pragma unroll
            for (int it = 0; it < 2; it++) {
                aP[it] = *(const float4*)&A[(size_t)(m0 + arow[it]) * K + k0 + 32 + akq[it]];
                bP[it] = *(const uint4*)&B[(size_t)(k0 + 32 + bkb[it]) * N + n0 + bnq[it]];
            }
        }
#pragma unroll
        for (int s = 0; s < 4; s++) {
            int k = s * 8;
            uint32_t a0 = As[(k + tig) * 68 + wm + gid];
            uint32_t a1 = As[(k + tig) * 68 + wm + gid + 8];
            uint32_t a2 = As[(k + 4 + tig) * 68 + wm + gid];
            uint32_t a3 = As[(k + 4 + tig) * 68 + wm + gid + 8];
#pragma unroll
            for (int j = 0; j < 4; j++) {
                uint32_t b0 = Bs[(k + tig) * 68 + wn + j * 8 + gid];
                uint32_t b1 = Bs[(k + 4 + tig) * 68 + wn + j * 8 + gid];
                mma_tf32(acc[j][0], acc[j][1], acc[j][2], acc[j][3], a0, a1, a2, a3, b0, b1);
            }
        }
        __syncthreads();
    }
#pragma unroll
    for (int j = 0; j < 4; j++) {
        int n = n0 + wn + j * 8 + tig * 2;
        int m = m0 + wm + gid;
        float v0 = acc[j][0], v1 = acc[j][1], v2 = acc[j][2], v3 = acc[j][3];
        if (bias) { float b0 = bias[n], b1 = bias[n + 1]; v0 += b0; v1 += b1; v2 += b0; v3 += b1; }
        size_t o0 = (size_t)m * N + n, o1 = (size_t)(m + 8) * N + n;
        C[o0] = v0; C[o0 + 1] = v1; C[o1] = v2; C[o1 + 1] = v3;
    }
}

// ---------------- head GEMM 128x128 (reg-prefetch) ----------------
__global__ __launch_bounds__(256) void hg_kernel(const float* __restrict__ A,
                                                 const float* __restrict__ B,
                                                 float* __restrict__ C,
                                                 int M, int N, int K) {
    __shared__ uint32_t As[32 * 132];
    __shared__ uint32_t Bs[32 * 132];
    int tid = threadIdx.x, lane = tid & 31, wid = tid >> 5;
    int wm = (wid & 3) * 32, wn = (wid >> 2) * 64;
    int m0 = blockIdx.y * 128, n0 = blockIdx.x * 128;
    int gid = lane >> 2, tig = lane & 3;
    int row4 = tid >> 3, kq4 = (tid & 7) * 4;
    float4 aP[4], bP[4];
#pragma unroll
    for (int it = 0; it < 4; it++) {
        aP[it] = *(const float4*)&A[(size_t)(m0 + row4 + it * 32) * K + kq4];
        bP[it] = *(const float4*)&B[(size_t)(n0 + row4 + it * 32) * K + kq4];
    }
    float acc[2][8][4];
#pragma unroll
    for (int mb = 0; mb < 2; mb++)
#pragma unroll
        for (int j = 0; j < 8; j++)
#pragma unroll
            for (int i = 0; i < 4; i++) acc[mb][j][i] = 0.f;

    for (int k0 = 0; k0 < K; k0 += 32) {
#pragma unroll
        for (int it = 0; it < 4; it++) {
            int row = row4 + it * 32;
            As[(kq4 + 0) * 132 + row] = f2tf32(aP[it].x);
            As[(kq4 + 1) * 132 + row] = f2tf32(aP[it].y);
            As[(kq4 + 2) * 132 + row] = f2tf32(aP[it].z);
            As[(kq4 + 3) * 132 + row] = f2tf32(aP[it].w);
            Bs[(kq4 + 0) * 132 + row] = f2tf32(bP[it].x);
            Bs[(kq4 + 1) * 132 + row] = f2tf32(bP[it].y);
            Bs[(kq4 + 2) * 132 + row] = f2tf32(bP[it].z);
            Bs[(kq4 + 3) * 132 + row] = f2tf32(bP[it].w);
        }
        __syncthreads();
        if (k0 + 32 < K) {
#pragma unroll
            for (int it = 0; it < 4; it++) {
                aP[it] = *(const float4*)&A[(size_t)(m0 + row4 + it * 32) * K + k0 + 32 + kq4];
                bP[it] = *(const float4*)&B[(size_t)(n0 + row4 + it * 32) * K + k0 + 32 + kq4];
            }
        }
#pragma unroll
        for (int s = 0; s < 4; s++) {
            int k = s * 8;
            uint32_t a[2][4];
#pragma unroll
            for (int mb = 0; mb < 2; mb++) {
                int mo = wm + mb * 16;
                a[mb][0] = As[(k + tig) * 132 + mo + gid];
                a[mb][1] = As[(k + tig) * 132 + mo + gid + 8];
                a[mb][2] = As[(k + 4 + tig) * 132 + mo + gid];
                a[mb][3] = As[(k + 4 + tig) * 132 + mo + gid + 8];
            }
#pragma unroll
            for (int j = 0; j < 8; j++) {
                uint32_t b0 = Bs[(k + tig) * 132 + wn + j * 8 + gid];
                uint32_t b1 = Bs[(k + 4 + tig) * 132 + wn + j * 8 + gid];
#pragma unroll
                for (int mb = 0; mb < 2; mb++)
                    mma_tf32(acc[mb][j][0], acc[mb][j][1], acc[mb][j][2], acc[mb][j][3],
                             a[mb][0], a[mb][1], a[mb][2], a[mb][3], b0, b1);
            }
        }
        __syncthreads();
    }
#pragma unroll
    for (int mb = 0; mb < 2; mb++)
#pragma unroll
        for (int j = 0; j < 8; j++) {
            int n = n0 + wn + j * 8 + tig * 2;
            int m = m0 + wm + mb * 16 + gid;
            size_t o0 = (size_t)m * N + n, o1 = (size_t)(m + 8) * N + n;
            C[o0] = acc[mb][j][0]; C[o0 + 1] = acc[mb][j][1];
            C[o1] = acc[mb][j][2]; C[o1 + 1] = acc[mb][j][3];
        }
}

// ---------------- flash attention (tf32): qtile=16, 256 threads ----------------
#define FA_SMEM ((16 * 520 + 64 * 68 + 16 * 68) * 4)
__global__ __launch_bounds__(256) void fattn_kernel(const float* __restrict__ q,
                                                    const float* __restrict__ k,
                                                    const float* __restrict__ v,
                                                    float* __restrict__ ctx) {
    extern __shared__ float sm[];
    float*    Ps  = sm;
    uint32_t* Ks  = (uint32_t*)(sm + 16 * 520);
    float*    Qs  = sm + 16 * 520 + 64 * 68;
    int qt = blockIdx.x;
    int bh = blockIdx.y;
    int b = bh >> 2, h = bh & 3;
    int tid = threadIdx.x, w = tid >> 5, lane = tid & 31;
    int gid = lane >> 2, tig = lane & 3;
    int q0 = qt * 16;
    int ktmax = (q0 + 79) / 64;

    {
        int row = tid >> 4, dq = (tid & 15) * 4;
        float4 t4 = *(const float4*)&q[(size_t)(b * SEQ + q0 + row) * 256 + h * 64 + dq];
        Qs[row * 68 + dq] = t4.x; Qs[row * 68 + dq + 1] = t4.y;
        Qs[row * 68 + dq + 2] = t4.z; Qs[row * 68 + dq + 3] = t4.w;
    }
    __syncthreads();
    uint32_t qa[8][4];
#pragma unroll
    for (int kb = 0; kb < 8; kb++) {
        qa[kb][0] = f2tf32(Qs[gid * 68 + kb * 8 + tig]);
        qa[kb][1] = f2tf32(Qs[(gid + 8) * 68 + kb * 8 + tig]);
        qa[kb][2] = f2tf32(Qs[gid * 68 + kb * 8 + tig + 4]);
        qa[kb][3] = f2tf32(Qs[(gid + 8) * 68 + kb * 8 + tig + 4]);
    }
    for (int kt = 0; kt < ktmax; kt++) {
        __syncthreads();
        for (int u = tid; u < 1024; u += 256) {
            int row = u >> 4, dq = (u & 15) * 4;
            float4 t4 = *(const float4*)&k[(size_t)(b * SEQ + kt * 64 + row) * 256 + h * 64 + dq];
            Ks[row * 68 + dq] = f2tf32(t4.x); Ks[row * 68 + dq + 1] = f2tf32(t4.y);
            Ks[row * 68 + dq + 2] = f2tf32(t4.z); Ks[row * 68 + dq + 3] = f2tf32(t4.w);
        }
        __syncthreads();
        float c0 = 0.f, c1 = 0.f, c2 = 0.f, c3 = 0.f;
#pragma unroll
        for (int kb = 0; kb < 8; kb++) {
            uint32_t b0 = Ks[(w * 8 + gid) * 68 + kb * 8 + tig];
            uint32_t b1 = Ks[(w * 8 + gid) * 68 + kb * 8 + tig + 4];
            mma_tf32(c0, c1, c2, c3, qa[kb][0], qa[kb][1], qa[kb][2], qa[kb][3], b0, b1);
        }
        int qg0 = q0 + gid, qg1 = qg0 + 8;
        int kg = kt * 64 + w * 8 + 2 * tig;
        Ps[gid * 520 + kg]           = (kg     <= qg0) ? c0 * 0.125f : -1e30f;
        Ps[gid * 520 + kg + 1]       = (kg + 1 <= qg0) ? c1 * 0.125f : -1e30f;
        Ps[(gid + 8) * 520 + kg]     = (kg     <= qg1) ? c2 * 0.125f : -1e30f;
        Ps[(gid + 8) * 520 + kg + 1] = (kg + 1 <= qg1) ? c3 * 0.125f : -1e30f;
    }
    __syncthreads();
    {
        int row = tid >> 4;
        int c0i = tid & 15;
        int ncols = ktmax * 64;
        float m = -1e30f;
        for (int c = c0i; c < ncols; c += 16) m = fmaxf(m, Ps[row * 520 + c]);
        m = fmaxf(m, __shfl_xor_sync(0xffffffffu, m, 1));
        m = fmaxf(m, __shfl_xor_sync(0xffffffffu, m, 2));
        m = fmaxf(m, __shfl_xor_sync(0xffffffffu, m, 4));
        m = fmaxf(m, __shfl_xor_sync(0xffffffffu, m, 8));
        float s = 0.f;
        for (int c = c0i; c < ncols; c += 16) {
            float e = expf(Ps[row * 520 + c] - m);
            Ps[row * 520 + c] = e;
            s += e;
        }
        s += __shfl_xor_sync(0xffffffffu, s, 1);
        s += __shfl_xor_sync(0xffffffffu, s, 2);
        s += __shfl_xor_sync(0xffffffffu, s, 4);
        s += __shfl_xor_sync(0xffffffffu, s, 8);
        float inv = 1.f / s;
        for (int c = c0i; c < ncols; c += 16)
            Ps[row * 520 + c] = __uint_as_float(f2tf32(Ps[row * 520 + c] * inv));
    }
    __syncthreads();
    uint32_t* Pu = (uint32_t*)Ps;
    float o0 = 0.f, o1 = 0.f, o2 = 0.f, o3 = 0.f;
    for (int kt = 0; kt < ktmax; kt++) {
        for (int u = tid; u < 1024; u += 256) {
            int row = u >> 4, dq = (u & 15) * 4;
            float4 t4 = *(const float4*)&v[(size_t)(b * SEQ + kt * 64 + row) * 256 + h * 64 + dq];
            Ks[row * 68 + dq] = f2tf32(t4.x); Ks[row * 68 + dq + 1] = f2tf32(t4.y);
            Ks[row * 68 + dq + 2] = f2tf32(t4.z); Ks[row * 68 + dq + 3] = f2tf32(t4.w);
        }
        __syncthreads();
#pragma unroll
        for (int kb = 0; kb < 8; kb++) {
            uint32_t a0 = Pu[gid * 520 + kt * 64 + kb * 8 + tig];
            uint32_t a1 = Pu[(gid + 8) * 520 + kt * 64 + kb * 8 + tig];
            uint32_t a2 = Pu[gid * 520 + kt * 64 + kb * 8 + tig + 4];
            uint32_t a3 = Pu[(gid + 8) * 520 + kt * 64 + kb * 8 + tig + 4];
            uint32_t b0 = Ks[(kb * 8 + tig) * 68 + w * 8 + gid];
            uint32_t b1 = Ks[(kb * 8 + 4 + tig) * 68 + w * 8 + gid];
            mma_tf32(o0, o1, o2, o3, a0, a1, a2, a3, b0, b1);
        }
        __syncthreads();
    }
    {
        int n = h * 64 + w * 8 + 2 * tig;
        size_t mrow = (size_t)(b * SEQ + q0 + gid);
        ctx[mrow * 256 + n] = o0;
        ctx[mrow * 256 + n + 1] = o1;
        ctx[(mrow + 8) * 256 + n] = o2;
        ctx[(mrow + 8) * 256 + n + 1] = o3;
    }
}

// ---------------- upfront: recipe softmax + neuron embeddings ----------------
__global__ void rsoft_all_kernel(const float* __restrict__ recipes, const float* __restrict__ basis,
                                 float* __restrict__ Rsoft_all, float* __restrict__ nemb_all) {
    int l = blockIdx.x;
    const float* rec = recipes + l * (NNEUR * NBASIS);
    float* Rsoft = Rsoft_all + l * (NNEUR * NBASIS);
    float* nemb  = nemb_all + l * (NNEUR * D_MODEL);
    int tid = threadIdx.x;
    __shared__ float rs[NNEUR * NBASIS];
    if (tid < NNEUR) {
        float row[NBASIS];
        float mx = -1e30f;
        for (int nb = 0; nb < NBASIS; nb++) { row[nb] = rec[tid * NBASIS + nb]; mx = fmaxf(mx, row[nb]); }
        float s = 0.f;
        for (int nb = 0; nb < NBASIS; nb++) { row[nb] = expf(row[nb] - mx); s += row[nb]; }
        float invs = 1.f / s;
        for (int nb = 0; nb < NBASIS; nb++) {
            float vv = row[nb] * invs;
            rs[tid * NBASIS + nb] = vv;
            Rsoft[tid * NBASIS + nb] = vv;
        }
    }
    __syncthreads();
    for (int i = tid; i < NNEUR * D_MODEL; i += 256) {
        int n = i >> 8, d = i & 255;
        float s = 0.f;
        for (int nb = 0; nb < NBASIS; nb++) s = fmaf(rs[n * NBASIS + nb], basis[nb * 256 + d], s);
        nemb[i] = s;
    }
}

// ---------------- upfront: neuron-core precompute (fp16 out, x2 blocking, neuron-split) ----------------
__global__ void ncore_all_kernel(const float* __restrict__ Rsoft_all,
                                 const float* __restrict__ A1, const float* __restrict__ A2,
                                 const float* __restrict__ B1, const float* __restrict__ B2,
                                 __half* __restrict__ NA1_all, __half* __restrict__ NA2_all,
                                 __half* __restrict__ NB1_all, __half* __restrict__ NB2_all) {
    int slot = blockIdx.y;                 // (l, arr, nhalf)
    int nh = slot & 1, arr = (slot >> 1) & 3, l = slot >> 3;
    const float* src; __half* dst; int esize;
    if (arr == 0)      { src = A1; dst = NA1_all + l * NA_SZ; esize = 8192; }
    else if (arr == 1) { src = A2; dst = NA2_all + l * NA_SZ; esize = 8192; }
    else if (arr == 2) { src = B1; dst = NB1_all + l * NB_SZ; esize = 16384; }
    else               { src = B2; dst = NB2_all + l * NB_SZ; esize = 16384; }
    __shared__ __align__(16) float rs[NNEUR * NBASIS];
    int tid = threadIdx.x;
    for (int i = tid; i < NNEUR * NBASIS; i += 256) rs[i] = Rsoft_all[l * (NNEUR * NBASIS) + i];
    __syncthreads();
    int e2 = blockIdx.x * 256 + tid;
    if (e2 >= esize / 2) return;
    int e = e2 * 2;
    float2 v[NBASIS];
#pragma unroll
    for (int nb = 0; nb < NBASIS; nb++) v[nb] = *(const float2*)&src[nb * esize + e];
    int n0 = nh * (NNEUR / 2);
    for (int n = n0; n < n0 + NNEUR / 2; n++) {
        const float4* rsr = (const float4*)&rs[n * NBASIS];
        float a0 = 0.f, a1 = 0.f;
#pragma unroll
        for (int q4 = 0; q4 < NBASIS / 4; q4++) {
            float4 r4 = rsr[q4];
            a0 = fmaf(r4.x, v[q4 * 4 + 0].x, a0); a1 = fmaf(r4.x, v[q4 * 4 + 0].y, a1);
            a0 = fmaf(r4.y, v[q4 * 4 + 1].x, a0); a1 = fmaf(r4.y, v[q4 * 4 + 1].y, a1);
            a0 = fmaf(r4.z, v[q4 * 4 + 2].x, a0); a1 = fmaf(r4.z, v[q4 * 4 + 2].y, a1);
            a0 = fmaf(r4.w, v[q4 * 4 + 3].x, a0); a1 = fmaf(r4.w, v[q4 * 4 + 3].y, a1);
        }
        *(__half2*)&dst[n * esize + e] = __floats2half2_rn(a0, a1);
    }
}

// ---------------- fused score + router (parallel warp top-k) ----------------
__global__ void scorerouter_kernel(const float* __restrict__ query, const float* __restrict__ nemb,
                                   int* __restrict__ topi, float* __restrict__ topw) {
    int t = blockIdx.x;
    int tid = threadIdx.x, warp = tid >> 5, lane = tid & 31;
    __shared__ float qrow[256];
    __shared__ float sc[NNEUR];
    __shared__ int   idxs[TOPK];
    __shared__ float wv[TOPK];
    qrow[tid] = query[t * 256 + tid];
    __syncthreads();
#pragma unroll
    for (int u = 0; u < 8; u++) {
        int n = warp * 8 + u;
        const float* nr = nemb + n * 256;
        float acc = 0.f;
#pragma unroll
        for (int i = 0; i < 8; i++) acc = fmaf(qrow[lane + 32 * i], nr[lane + 32 * i], acc);
#pragma unroll
        for (int o = 16; o; o >>= 1) acc += __shfl_down_sync(0xffffffffu, acc, o);
        if (!lane) sc[n] = acc;
    }
    __syncthreads();
    if (warp == 0) {
        float vals[TOPK];
#pragma unroll
        for (int kk = 0; kk < TOPK; kk++) {
            float v0 = sc[lane], v1 = sc[lane + 32];
            int i0 = lane, i1 = lane + 32;
            if (v1 > v0) { v0 = v1; i0 = i1; }
#pragma unroll
            for (int o = 16; o; o >>= 1) {
                float ov = __shfl_down_sync(0xffffffffu, v0, o);
                int oi = __shfl_down_sync(0xffffffffu, i0, o);
                if (ov > v0) { v0 = ov; i0 = oi; }
            }
            v0 = __shfl_sync(0xffffffffu, v0, 0);
            i0 = __shfl_sync(0xffffffffu, i0, 0);
            vals[kk] = v0;
            if (lane == 0) { idxs[kk] = i0; sc[i0] = -1e30f; }
            __syncwarp();
        }
        if (lane == 0) {
            float mx = vals[0];
            float e[TOPK], s = 0.f;
#pragma unroll
            for (int kk = 0; kk < TOPK; kk++) { e[kk] = expf(vals[kk] - mx); s += e[kk]; }
            float invs = 1.f / s;
#pragma unroll
            for (int kk = 0; kk < TOPK; kk++) wv[kk] = e[kk] * invs;
        }
    }
    __syncthreads();
    if (tid < TOPK) {
        topi[t * TOPK + tid] = idxs[tid];
        topw[t * TOPK + tid] = wv[tid];
    }
}

// ---------------- TT FFN stage A ----------------
struct SmemA {
    float N1[NNEUR * 128];
    float N2[NNEUR * 128];
    float xf_t[TPB_A][256];
    float a1[16][128];
    float a2t[16][128];
    float tt[16][128];
};

__global__ __launch_bounds__(512) void stageA_kernel(
        const float* __restrict__ xin, const float* __restrict__ n2g, const float* __restrict__ n2b,
        const int* __restrict__ topi, const float* __restrict__ topw,
        const __half* __restrict__ NA1, const __half* __restrict__ NA2,
        float* __restrict__ hpart) {
    extern __shared__ float smemraw[];
    SmemA& S = *reinterpret_cast<SmemA*>(smemraw);
    int tid = threadIdx.x, tg = tid >> 5, lane = tid & 31;
    int t0 = blockIdx.x * TPB_A;
    int r0 = blockIdx.y * RPER_A;
#pragma unroll
    for (int tok = 0; tok < 2; tok++) {
        int t = t0 + tg * 2 + tok;
        float vals[8];
        float s = 0.f, s2 = 0.f;
#pragma unroll
        for (int qd = 0; qd < 8; qd++) {
            float v = xin[t * 256 + lane + 32 * qd];
            vals[qd] = v; s += v; s2 = fmaf(v, v, s2);
        }
#pragma unroll
        for (int o = 16; o; o >>= 1) {
            s += __shfl_xor_sync(0xffffffffu, s, o);
            s2 += __shfl_xor_sync(0xffffffffu, s2, o);
        }
        float mean = s * (1.f / 256.f);
        float var = s2 * (1.f / 256.f) - mean * mean;
        float inv = rsqrtf(var + 1e-5f);
#pragma unroll
        for (int qd = 0; qd < 8; qd++) {
            int d = lane + 32 * qd;
            float nv = (vals[qd] - mean) * inv * n2g[d] + n2b[d];
            S.xf_t[tg * 2 + tok][(d & 15) * 16 + (d >> 4)] = nv;
        }
    }
    int nid[2][TOPK]; float nw[2][TOPK];
#pragma unroll
    for (int tok = 0; tok < 2; tok++) {
        int t = t0 + tg * 2 + tok;
#pragma unroll
        for (int kk = 0; kk < TOPK; kk++) { nid[tok][kk] = topi[t * TOPK + kk]; nw[tok][kk] = topw[t * TOPK + kk]; }
    }
    float hacc[2][2] = {{0.f, 0.f}, {0.f, 0.f}};
    int o = lane * 4;
    int jrow = lane >> 1;
    int kk0 = (lane & 1) * 4;
    int kq2 = lane >> 2;
    int l0 = (lane * 2) & 7, l1 = (lane * 2 + 1) & 7;

    for (int ri = 0; ri < RPER_A; ri++) {
        int r = r0 + ri;
        __syncthreads();
#pragma unroll
        for (int it = 0; it < 2; it++) {
            int u = tid + it * 512;
            int n = u >> 4, rest = u & 15;
            uint4 p1 = *(const uint4*)&NA1[(size_t)n * 8192 + rest * 512 + r * 8];
            h8_to_f8(p1, &S.N1[n * 128 + rest * 8]);
            uint4 p2 = *(const uint4*)&NA2[(size_t)n * 8192 + r * 128 + rest * 8];
            h8_to_f8(p2, &S.N2[n * 128 + rest * 8]);
        }
        __syncthreads();
#pragma unroll
        for (int tok = 0; tok < 2; tok++) {
            int xrow = tg * 2 + tok;
            float4 m1 = make_float4(0.f, 0.f, 0.f, 0.f);
            float4 m2 = make_float4(0.f, 0.f, 0.f, 0.f);
#pragma unroll
            for (int kk = 0; kk < TOPK; kk++) {
                float ww = nw[tok][kk];
                float4 s1 = *(const float4*)&S.N1[nid[tok][kk] * 128 + o];
                float4 s2 = *(const float4*)&S.N2[nid[tok][kk] * 128 + o];
                m1.x = fmaf(ww, s1.x, m1.x); m1.y = fmaf(ww, s1.y, m1.y);
                m1.z = fmaf(ww, s1.z, m1.z); m1.w = fmaf(ww, s1.w, m1.w);
                m2.x = fmaf(ww, s2.x, m2.x); m2.y = fmaf(ww, s2.y, m2.y);
                m2.z = fmaf(ww, s2.z, m2.z); m2.w = fmaf(ww, s2.w, m2.w);
            }
            *(float4*)&S.a1[tg][o] = m1;
            {
                int j = o >> 3, l = o & 7;
                S.a2t[tg][(l + 0) * 16 + j] = m2.x;
                S.a2t[tg][(l + 1) * 16 + j] = m2.y;
                S.a2t[tg][(l + 2) * 16 + j] = m2.z;
                S.a2t[tg][(l + 3) * 16 + j] = m2.w;
            }
            __syncwarp();
            {
                float t0r = 0.f, t1r = 0.f, t2r = 0.f, t3r = 0.f;
#pragma unroll
                for (int i = 0; i < 16; i++) {
                    float xv = S.xf_t[xrow][jrow * 16 + i];
                    float4 av = *(const float4*)&S.a1[tg][i * 8 + kk0];
                    t0r = fmaf(xv, av.x, t0r); t1r = fmaf(xv, av.y, t1r);
                    t2r = fmaf(xv, av.z, t2r); t3r = fmaf(xv, av.w, t3r);
                }
                S.tt[tg][(kk0 + 0) * 16 + jrow] = t0r;
                S.tt[tg][(kk0 + 1) * 16 + jrow] = t1r;
                S.tt[tg][(kk0 + 2) * 16 + jrow] = t2r;
                S.tt[tg][(kk0 + 3) * 16 + jrow] = t3r;
            }
            __syncwarp();
            {
                float s0 = 0.f, s1 = 0.f;
#pragma unroll
                for (int j4 = 0; j4 < 4; j4++) {
                    float4 tv = *(const float4*)&S.tt[tg][kq2 * 16 + j4 * 4];
                    float4 a0 = *(const float4*)&S.a2t[tg][l0 * 16 + j4 * 4];
                    float4 a1v = *(const float4*)&S.a2t[tg][l1 * 16 + j4 * 4];
                    s0 = fmaf(tv.x, a0.x, s0); s0 = fmaf(tv.y, a0.y, s0);
                    s0 = fmaf(tv.z, a0.z, s0); s0 = fmaf(tv.w, a0.w, s0);
                    s1 = fmaf(tv.x, a1v.x, s1); s1 = fmaf(tv.y, a1v.y, s1);
                    s1 = fmaf(tv.z, a1v.z, s1); s1 = fmaf(tv.w, a1v.w, s1);
                }
                hacc[tok][0] += s0;
                hacc[tok][1] += s1;
            }
            __syncwarp();
        }
    }
#pragma unroll
    for (int tok = 0; tok < 2; tok++) {
        int t = t0 + tg * 2 + tok;
        hpart[(blockIdx.y * T_TOK + t) * 64 + lane * 2]     = hacc[tok][0];
        hpart[(blockIdx.y * T_TOK + t) * 64 + lane * 2 + 1] = hacc[tok][1];
    }
}

// ---------------- TT FFN stage B ----------------
#define TRS 12
struct SmemB {
    float N1[NNEUR * 256];
    float N2[NNEUR * 256];
    float trT[16][32 * TRS];
    float hfT[TPB_B][64];
};

__global__ __launch_bounds__(512) void stageB_kernel(
        const float* __restrict__ hpart, const int* __restrict__ topi, const float* __restrict__ topw,
        const __half* __restrict__ NB1, const __half* __restrict__ NB2,
        float* __restrict__ ffnpart) {
    extern __shared__ float smemraw[];
    SmemB& S = *reinterpret_cast<SmemB*>(smemraw);
    int tid = threadIdx.x, tg = tid >> 5, lane = tid & 31;
    int t0 = blockIdx.x * TPB_B;
    int r0 = blockIdx.y * RPER_B;
    for (int u = tid; u < TPB_B * 64; u += 512) {
        float s = 0.f;
#pragma unroll
        for (int g = 0; g < RG_A; g++) s += hpart[g * (T_TOK * 64) + t0 * 64 + u];
        int tok = u >> 6, e = u & 63;
        S.hfT[tok][(e & 7) * 8 + (e >> 3)] = s;
    }
    __syncthreads();
    int nid[2][TOPK]; float nw[2][TOPK];
#pragma unroll
    for (int tok = 0; tok < 2; tok++) {
        int t = t0 + tg * 2 + tok;
#pragma unroll
        for (int kk = 0; kk < TOPK; kk++) { nid[tok][kk] = topi[t * TOPK + kk]; nw[tok][kk] = topw[t * TOPK + kk]; }
    }
    float oreg[2][32];
#pragma unroll
    for (int tok = 0; tok < 2; tok++)
#pragma unroll
        for (int i = 0; i < 32; i++) oreg[tok][i] = 0.f;

    for (int ri = 0; ri < RPER_B; ri++) {
        int r = r0 + ri;
        __syncthreads();
#pragma unroll
        for (int it = 0; it < 8; it++) {
            int u = tid + it * 512;
            if (u < 2048) {
                int n = u >> 5, rest = u & 31;
                int i = rest >> 2, kq = (rest & 3) * 8;
                uint4 p = *(const uint4*)&NB1[(size_t)n * 16384 + i * 2048 + r * 32 + kq];
                h8_to_f8(p, &S.N1[n * 256 + i * 32 + kq]);
            } else {
                int u2 = u - 2048;
                int n = u2 >> 5, c = (u2 & 31) * 8;
                uint4 p = *(const uint4*)&NB2[(size_t)n * 16384 + r * 256 + c];
                h8_to_f8(p, &S.N2[n * 256 + c]);
            }
        }
        __syncthreads();
#pragma unroll
        for (int tok = 0; tok < 2; tok++) {
            int xrow = tg * 2 + tok;
            float b1r[8], b2r[8];
#pragma unroll
            for (int i = 0; i < 8; i++) {
                float s1 = 0.f, s2 = 0.f;
#pragma unroll
                for (int kk = 0; kk < TOPK; kk++) {
                    s1 = fmaf(nw[tok][kk], S.N1[nid[tok][kk] * 256 + i * 32 + lane], s1);
                    s2 = fmaf(nw[tok][kk], S.N2[nid[tok][kk] * 256 + i * 32 + lane], s2);
                }
                b1r[i] = s1; b2r[i] = s2;
            }
#pragma unroll
            for (int j2 = 0; j2 < 4; j2++) {
                float4 h0 = *(const float4*)&S.hfT[xrow][(j2 * 2) * 8];
                float4 h1 = *(const float4*)&S.hfT[xrow][(j2 * 2) * 8 + 4];
                float sA = h0.x * b1r[0] + h0.y * b1r[1] + h0.z * b1r[2] + h0.w * b1r[3]
                         + h1.x * b1r[4] + h1.y * b1r[5] + h1.z * b1r[6] + h1.w * b1r[7];
                float4 g0 = *(const float4*)&S.hfT[xrow][(j2 * 2 + 1) * 8];
                float4 g1 = *(const float4*)&S.hfT[xrow][(j2 * 2 + 1) * 8 + 4];
                float sB = g0.x * b1r[0] + g0.y * b1r[1] + g0.z * b1r[2] + g0.w * b1r[3]
                         + g1.x * b1r[4] + g1.y * b1r[5] + g1.z * b1r[6] + g1.w * b1r[7];
                *(float2*)&S.trT[tg][lane * TRS + j2 * 2] = make_float2(sA, sB);
            }
            __syncwarp();
#pragma unroll
            for (int kk = 0; kk < 32; kk++) {
                float4 t0v = *(const float4*)&S.trT[tg][kk * TRS];
                float4 t1v = *(const float4*)&S.trT[tg][kk * TRS + 4];
                float s = t0v.x * b2r[0] + t0v.y * b2r[1] + t0v.z * b2r[2] + t0v.w * b2r[3]
                        + t1v.x * b2r[4] + t1v.y * b2r[5] + t1v.z * b2r[6] + t1v.w * b2r[7];
                oreg[tok][kk] += s;
            }
            __syncwarp();
        }
    }
#pragma unroll
    for (int tok = 0; tok < 2; tok++) {
        int t = t0 + tg * 2 + tok;
        float* dst = ffnpart + (blockIdx.y * T_TOK + t) * (size_t)DFF;
#pragma unroll
        for (int kk = 0; kk < 32; kk++) dst[kk * 32 + lane] = oreg[tok][kk];
    }
}

__global__ void gelu_reduce_kernel(const float* __restrict__ ffnpart, float* __restrict__ ffn) {
    int idx = blockIdx.x * 256 + threadIdx.x;
    float4 s = ((const float4*)ffnpart)[idx];
#pragma unroll
    for (int g = 1; g < RG_B; g++) {
        float4 p = ((const float4*)(ffnpart + (size_t)g * (T_TOK * DFF)))[idx];
        s.x += p.x; s.y += p.y; s.z += p.z; s.w += p.w;
    }
    float4 r;
    r.x = 0.5f * s.x * (1.f + erff(s.x * 0.70710678118654752f));
    r.y = 0.5f * s.y * (1.f + erff(s.y * 0.70710678118654752f));
    r.z = 0.5f * s.z * (1.f + erff(s.z * 0.70710678118654752f));
    r.w = 0.5f * s.w * (1.f + erff(s.w * 0.70710678118654752f));
    ((float4*)ffn)[idx] = r;
}

// ---------------- host orchestration ----------------
extern "C" void kernel_launch(void* const* d_in, const int* in_sizes, int n_in,
                              void* d_out, int out_size) {
    const int*   ids    = (const int*)d_in[0];
    const float* te     = (const float*)d_in[1];
    const float* pe     = (const float*)d_in[2];
    const float* qW     = (const float*)d_in[3];
    const float* qb     = (const float*)d_in[4];
    const float* kW     = (const float*)d_in[5];
    const float* kb     = (const float*)d_in[6];
    const float* vW     = (const float*)d_in[7];
    const float* vb     = (const float*)d_in[8];
    const float* sW     = (const float*)d_in[9];
    const float* sb     = (const float*)d_in[10];
    const float* recipes= (const float*)d_in[11];
    const float* wdW    = (const float*)d_in[12];
    const float* wdb    = (const float*)d_in[13];
    const float* n1g    = (const float*)d_in[14];
    const float* n1b    = (const float*)d_in[15];
    const float* n2g    = (const float*)d_in[16];
    const float* n2b    = (const float*)d_in[17];
    const float* basis  = (const float*)d_in[18];
    const float* A1     = (const float*)d_in[19];
    const float* A2     = (const float*)d_in[20];
    const float* B1     = (const float*)d_in[21];
    const float* B2     = (const float*)d_in[22];
    const float* fng    = (const float*)d_in[23];
    const float* fnb    = (const float*)d_in[24];
    float* out = (float*)d_out;

    float *x, *nrm1, *q, *k, *v, *ctx, *query, *ffn, *Rsoft, *nemb, *hpart, *ffnpart, *wdpart;
    float *topw;
    __half *NA1, *NA2, *NB1, *NB2;
    int* topi;
    uint32_t *qW32, *kW32, *vW32, *sW32, *wdW32;
    cudaGetSymbolAddress((void**)&x, g_x);
    cudaGetSymbolAddress((void**)&nrm1, g_nrm1);
    cudaGetSymbolAddress((void**)&q, g_q);
    cudaGetSymbolAddress((void**)&k, g_k);
    cudaGetSymbolAddress((void**)&v, g_v);
    cudaGetSymbolAddress((void**)&ctx, g_ctx);
    cudaGetSymbolAddress((void**)&query, g_query);
    cudaGetSymbolAddress((void**)&ffn, g_ffn);
    cudaGetSymbolAddress((void**)&Rsoft, g_Rsoft);
    cudaGetSymbolAddress((void**)&nemb, g_nemb);
    cudaGetSymbolAddress((void**)&hpart, g_hpart);
    cudaGetSymbolAddress((void**)&ffnpart, g_ffnpart);
    cudaGetSymbolAddress((void**)&wdpart, g_wdpart);
    cudaGetSymbolAddress((void**)&NA1, g_NA1);
    cudaGetSymbolAddress((void**)&NA2, g_NA2);
    cudaGetSymbolAddress((void**)&NB1, g_NB1);
    cudaGetSymbolAddress((void**)&NB2, g_NB2);
    cudaGetSymbolAddress((void**)&topi, g_topi);
    cudaGetSymbolAddress((void**)&topw, g_topw);
    cudaGetSymbolAddress((void**)&qW32, g_qW32);
    cudaGetSymbolAddress((void**)&kW32, g_kW32);
    cudaGetSymbolAddress((void**)&vW32, g_vW32);
    cudaGetSymbolAddress((void**)&sW32, g_sW32);
    cudaGetSymbolAddress((void**)&wdW32, g_wdW32);

    cudaFuncSetAttribute(stageA_kernel, cudaFuncAttributeMaxDynamicSharedMemorySize, (int)sizeof(SmemA));
    cudaFuncSetAttribute(stageB_kernel, cudaFuncAttributeMaxDynamicSharedMemorySize, (int)sizeof(SmemB));
    cudaFuncSetAttribute(fattn_kernel, cudaFuncAttributeMaxDynamicSharedMemorySize, FA_SMEM);

    // upfront
    embed_kernel<<<T_TOK, 256>>>(ids, te, pe, x);
    Cvt5 cj;
    cj.src[0] = qW;  cj.dst[0] = qW32;  cj.n[0] = NLAYER * 65536;
    cj.src[1] = kW;  cj.dst[1] = kW32;  cj.n[1] = NLAYER * 65536;
    cj.src[2] = vW;  cj.dst[2] = vW32;  cj.n[2] = NLAYER * 65536;
    cj.src[3] = sW;  cj.dst[3] = sW32;  cj.n[3] = NLAYER * 131072;
    cj.src[4] = wdW; cj.dst[4] = wdW32; cj.n[4] = NLAYER * 262144;
    cvt5_kernel<<<dim3(NLAYER * 262144 / 256, 5), 256>>>(cj);
    rsoft_all_kernel<<<NLAYER, 256>>>(recipes, basis, Rsoft, nemb);
    ncore_all_kernel<<<dim3(32, 8 * NLAYER), 256>>>(Rsoft, A1, A2, B1, B2, NA1, NA2, NB1, NB2);

    for (int l = 0; l < NLAYER; l++) {
        ln_kernel<<<T_TOK / 8, 256>>>(x, n1g + l * 256, n1b + l * 256, nrm1);
        W4u gb;
        gb.W[0] = qW32 + l * 65536;  gb.bias[0] = qb + l * 256; gb.out[0] = q;
        gb.W[1] = kW32 + l * 65536;  gb.bias[1] = kb + l * 256; gb.out[1] = k;
        gb.W[2] = vW32 + l * 65536;  gb.bias[2] = vb + l * 256; gb.out[2] = v;
        gb.W[3] = sW32 + l * 131072; gb.bias[3] = nullptr;      gb.out[3] = query;
        tc_gemmb<<<dim3(4, 16, 4), 256>>>(nrm1, gb, 1024, 256, 256);
        fattn_kernel<<<dim3(SEQ / 16, 8), 256, FA_SMEM>>>(q, k, v, ctx);
        tc_gemm_sk<<<dim3(4, 16, 2), 256>>>(ctx, sW32 + l * 131072 + 65536, wdpart, 256, 256, 128);
        wdadd_kernel<<<T_TOK, 256>>>(wdpart, sb + l * 256, query);
        scorerouter_kernel<<<T_TOK, 256>>>(query, nemb + l * (NNEUR * D_MODEL), topi, topw);
        stageA_kernel<<<dim3(T_TOK / TPB_A, RG_A), 512, sizeof(SmemA)>>>(
            x, n2g + l * 256, n2b + l * 256, topi, topw, NA1 + l * NA_SZ, NA2 + l * NA_SZ, hpart);
        stageB_kernel<<<dim3(T_TOK / TPB_B, RG_B), 512, sizeof(SmemB)>>>(
            hpart, topi, topw, NB1 + l * NB_SZ, NB2 + l * NB_SZ, ffnpart);
        gelu_reduce_kernel<<<T_TOK * DFF / 1024, 256>>>(ffnpart, ffn);
        tc_gemm_sk<<<dim3(4, 16, 2), 256>>>(ffn, wdW32 + l * 262144, wdpart, 256, 1024, 512);
        wdadd_kernel<<<T_TOK, 256>>>(wdpart, wdb + l * 256, x);
    }
    ln_kernel<<<T_TOK / 8, 256>>>(x, fng, fnb, nrm1);
    hg_kernel<<<dim3(VOCAB / 128, T_TOK / 128), 256>>>(nrm1, te, out, 1024, VOCAB, 256);
}

// round 16
// speedup vs baseline: 1.0012x; 1.0012x over previous
#include <cuda_runtime.h>
#include <cuda_bf16.h>
#include <cuda_fp16.h>
#include <math.h>
#include <stdint.h>

// ---------------- constants ----------------
#define T_TOK   1024
#define D_MODEL 256
#define SEQ     512
#define NHEAD   4
#define DHEAD   64
#define NBASIS  32
#define RRANK   64
#define NNEUR   64
#define TOPK    8
#define DFF     1024
#define NLAYER  4
#define VOCAB   32000
#define TPB_A   32
#define RG_A    8
#define RPER_A  (RRANK / RG_A)
#define TPB_B   32
#define RG_B    4
#define RPER_B  (RRANK / RG_B)
#define NA_SZ   (NNEUR * 8192)
#define NB_SZ   (NNEUR * 16384)

// ---------------- scratch ----------------
__device__ float g_x[T_TOK * D_MODEL];
__device__ float g_nrm1[T_TOK * D_MODEL];
__device__ float g_q[T_TOK * D_MODEL];
__device__ float g_k[T_TOK * D_MODEL];
__device__ float g_v[T_TOK * D_MODEL];
__device__ float g_ctx[T_TOK * D_MODEL];
__device__ float g_query[T_TOK * D_MODEL];
__device__ float g_ffn[T_TOK * DFF];
__device__ float g_Rsoft[NLAYER * NNEUR * NBASIS];
__device__ float g_nemb[NLAYER * NNEUR * D_MODEL];
__device__ float g_hpart[RG_A * T_TOK * 64];
__device__ float g_ffnpart[RG_B * T_TOK * DFF];
__device__ float g_wdpart[2 * T_TOK * D_MODEL];
__device__ int   g_topi[T_TOK * TOPK];
__device__ float g_topw[T_TOK * TOPK];
__device__ __half g_NA1[NLAYER * NA_SZ];
__device__ __half g_NA2[NLAYER * NA_SZ];
__device__ __half g_NB1[NLAYER * NB_SZ];
__device__ __half g_NB2[NLAYER * NB_SZ];
__device__ uint32_t g_qW32[NLAYER * 65536];
__device__ uint32_t g_kW32[NLAYER * 65536];
__device__ uint32_t g_vW32[NLAYER * 65536];
__device__ uint32_t g_sW32[NLAYER * 131072];
__device__ uint32_t g_wdW32[NLAYER * 262144];

// ---------------- tf32 helpers ----------------
__device__ __forceinline__ uint32_t f2tf32(float f) {
    uint32_t u;
    asm("cvt.rna.tf32.f32 %0, %1;" : "=r"(u) : "f"(f));
    return u;
}
__device__ __forceinline__ void mma_tf32(float& c0, float& c1, float& c2, float& c3,
                                         uint32_t a0, uint32_t a1, uint32_t a2, uint32_t a3,
                                         uint32_t b0, uint32_t b1) {
    asm("mma.sync.aligned.m16n8k8.row.col.f32.tf32.tf32.f32 "
        "{%0,%1,%2,%3},{%4,%5,%6,%7},{%8,%9},{%0,%1,%2,%3};"
        : "+f"(c0), "+f"(c1), "+f"(c2), "+f"(c3)
        : "r"(a0), "r"(a1), "r"(a2), "r"(a3), "r"(b0), "r"(b1));
}
__device__ __forceinline__ void h8_to_f8(uint4 p, float* dst) {
    const __half2* h = (const __half2*)&p;
#pragma unroll
    for (int i = 0; i < 4; i++) {
        float2 f = __half22float2(h[i]);
        dst[2 * i] = f.x; dst[2 * i + 1] = f.y;
    }
}

// ---------------- merged upfront conversion ----------------
struct Cvt5 { const float* src[5]; uint32_t* dst[5]; int n[5]; };
__global__ void cvt5_kernel(Cvt5 j) {
    int a = blockIdx.y;
    int i = blockIdx.x * 256 + threadIdx.x;
    if (i < j.n[a]) j.dst[a][i] = f2tf32(j.src[a][i]);
}

// ---------------- embed ----------------
__global__ void embed_kernel(const int* __restrict__ ids, const float* __restrict__ te,
                             const float* __restrict__ pe, float* __restrict__ x) {
    int t = blockIdx.x, d = threadIdx.x;
    int s = t & (SEQ - 1);
    x[t * 256 + d] = te[ids[t] * 256 + d] + pe[s * 256 + d];
}

// ---------------- layernorm: warp per token ----------------
__global__ void ln_kernel(const float* __restrict__ x, const float* __restrict__ g,
                          const float* __restrict__ b, float* __restrict__ out) {
    int warp = threadIdx.x >> 5, lane = threadIdx.x & 31;
    int t = blockIdx.x * 8 + warp;
    float vals[8];
    float s = 0.f, s2 = 0.f;
#pragma unroll
    for (int qd = 0; qd < 8; qd++) {
        float v = x[t * 256 + lane + 32 * qd];
        vals[qd] = v; s += v; s2 = fmaf(v, v, s2);
    }
#pragma unroll
    for (int o = 16; o; o >>= 1) {
        s += __shfl_xor_sync(0xffffffffu, s, o);
        s2 += __shfl_xor_sync(0xffffffffu, s2, o);
    }
    float mean = s * (1.f / 256.f);
    float var = s2 * (1.f / 256.f) - mean * mean;
    float inv = rsqrtf(var + 1e-5f);
#pragma unroll
    for (int qd = 0; qd < 8; qd++) {
        int d = lane + 32 * qd;
        out[t * 256 + d] = (vals[qd] - mean) * inv * g[d] + b[d];
    }
}

// ---------------- split-K tf32 GEMM (reg-prefetch), partial out ----------------
__global__ __launch_bounds__(256) void tc_gemm_sk(const float* __restrict__ A,
                                                  const uint32_t* __restrict__ B,
                                                  float* __restrict__ Cpart,
                                                  int N, int K, int klen) {
    __shared__ uint32_t As[32 * 68];
    __shared__ uint32_t Bs[32 * 68];
    int tid = threadIdx.x, lane = tid & 31, wid = tid >> 5;
    int wm = (wid & 3) * 16, wn = (wid >> 2) * 32;
    int m0 = blockIdx.y * 64, n0 = blockIdx.x * 64;
    int gid = lane >> 2, tig = lane & 3;
    int kbeg = blockIdx.z * klen;
    float* C = Cpart + (size_t)blockIdx.z * T_TOK * D_MODEL;
    int arow[2], akq[2], bkb[2], bnq[2];
#pragma unroll
    for (int it = 0; it < 2; it++) {
        int u = tid + it * 256;
        arow[it] = u >> 3; akq[it] = (u & 7) * 4;
        bkb[it] = u >> 4; bnq[it] = (u & 15) * 4;
    }
    float4 aP[2]; uint4 bP[2];
#pragma unroll
    for (int it = 0; it < 2; it++) {
        aP[it] = *(const float4*)&A[(size_t)(m0 + arow[it]) * K + kbeg + akq[it]];
        bP[it] = *(const uint4*)&B[(size_t)(kbeg + bkb[it]) * N + n0 + bnq[it]];
    }
    float acc[4][4];
#pragma unroll
    for (int j = 0; j < 4; j++)
#pragma unroll
        for (int i = 0; i < 4; i++) acc[j][i] = 0.f;

    for (int k0 = kbeg; k0 < kbeg + klen; k0 += 32) {
#pragma unroll
        for (int it = 0; it < 2; it++) {
            As[(akq[it] + 0) * 68 + arow[it]] = f2tf32(aP[it].x);
            As[(akq[it] + 1) * 68 + arow[it]] = f2tf32(aP[it].y);
            As[(akq[it] + 2) * 68 + arow[it]] = f2tf32(aP[it].z);
            As[(akq[it] + 3) * 68 + arow[it]] = f2tf32(aP[it].w);
            *(uint4*)&Bs[bkb[it] * 68 + bnq[it]] = bP[it];
        }
        __syncthreads();
        if (k0 + 32 < kbeg + klen) {
#pragma unroll
            for (int it = 0; it < 2; it++) {
                aP[it] = *(const float4*)&A[(size_t)(m0 + arow[it]) * K + k0 + 32 + akq[it]];
                bP[it] = *(const uint4*)&B[(size_t)(k0 + 32 + bkb[it]) * N + n0 + bnq[it]];
            }
        }
#pragma unroll
        for (int s = 0; s < 4; s++) {
            int k = s * 8;
            uint32_t a0 = As[(k + tig) * 68 + wm + gid];
            uint32_t a1 = As[(k + tig) * 68 + wm + gid + 8];
            uint32_t a2 = As[(k + 4 + tig) * 68 + wm + gid];
            uint32_t a3 = As[(k + 4 + tig) * 68 + wm + gid + 8];
#pragma unroll
            for (int j = 0; j < 4; j++) {
                uint32_t b0 = Bs[(k + tig) * 68 + wn + j * 8 + gid];
                uint32_t b1 = Bs[(k + 4 + tig) * 68 + wn + j * 8 + gid];
                mma_tf32(acc[j][0], acc[j][1], acc[j][2], acc[j][3], a0, a1, a2, a3, b0, b1);
            }
        }
        __syncthreads();
    }
#pragma unroll
    for (int j = 0; j < 4; j++) {
        int n = n0 + wn + j * 8 + tig * 2;
        int m = m0 + wm + gid;
        size_t o0 = (size_t)m * N + n, o1 = (size_t)(m + 8) * N + n;
        C[o0] = acc[j][0]; C[o0 + 1] = acc[j][1]; C[o1] = acc[j][2]; C[o1 + 1] = acc[j][3];
    }
}

// combine: x += p0 + p1 + bias
__global__ void wdadd_kernel(const float* __restrict__ p, const float* __restrict__ bias,
                             float* __restrict__ x) {
    int idx = blockIdx.x * 256 + threadIdx.x;
    x[idx] += p[idx] + p[T_TOK * D_MODEL + idx] + bias[idx & 255];
}

// ---------------- batched tf32 GEMM (reg-prefetch, 4 weights) ----------------
struct W4u { const uint32_t* W[4]; const float* bias[4]; float* out[4]; };

__global__ __launch_bounds__(256) void tc_gemmb(const float* __restrict__ A, W4u gb,
                                                int M, int N, int K) {
    const uint32_t* __restrict__ B = gb.W[blockIdx.z];
    const float* __restrict__ bias = gb.bias[blockIdx.z];
    float* __restrict__ C = gb.out[blockIdx.z];
    __shared__ uint32_t As[32 * 68];
    __shared__ uint32_t Bs[32 * 68];
    int tid = threadIdx.x, lane = tid & 31, wid = tid >> 5;
    int wm = (wid & 3) * 16, wn = (wid >> 2) * 32;
    int m0 = blockIdx.y * 64, n0 = blockIdx.x * 64;
    int gid = lane >> 2, tig = lane & 3;
    int arow[2], akq[2], bkb[2], bnq[2];
#pragma unroll
    for (int it = 0; it < 2; it++) {
        int u = tid + it * 256;
        arow[it] = u >> 3; akq[it] = (u & 7) * 4;
        bkb[it] = u >> 4; bnq[it] = (u & 15) * 4;
    }
    float4 aP[2]; uint4 bP[2];
#pragma unroll
    for (int it = 0; it < 2; it++) {
        aP[it] = *(const float4*)&A[(size_t)(m0 + arow[it]) * K + akq[it]];
        bP[it] = *(const uint4*)&B[(size_t)bkb[it] * N + n0 + bnq[it]];
    }
    float acc[4][4];
#pragma unroll
    for (int j = 0; j < 4; j++)
#pragma unroll
        for (int i = 0; i < 4; i++) acc[j][i] = 0.f;

    for (int k0 = 0; k0 < K; k0 += 32) {
#pragma unroll
        for (int it = 0; it < 2; it++) {
            As[(akq[it] + 0) * 68 + arow[it]] = f2tf32(aP[it].x);
            As[(akq[it] + 1) * 68 + arow[it]] = f2tf32(aP[it].y);
            As[(akq[it] + 2) * 68 + arow[it]] = f2tf32(aP[it].z);
            As[(akq[it] + 3) * 68 + arow[it]] = f2tf32(aP[it].w);
            *(uint4*)&Bs[bkb[it] * 68 + bnq[it]] = bP[it];
        }
        __syncthreads();
        if (k0 + 32 < K) {
#pragma unroll
            for (int it = 0; it < 2; it++) {
                aP[it] = *(const float4*)&A[(size_t)(m0 + arow[it]) * K + k0 + 32 + akq[it]];
                bP[it] = *(const uint4*)&B[(size_t)(k0 + 32 + bkb[it]) * N + n0 + bnq[it]];
            }
        }
#pragma unroll
        for (int s = 0; s < 4; s++) {
            int k = s * 8;
            uint32_t a0 = As[(k + tig) * 68 + wm + gid];
            uint32_t a1 = As[(k + tig) * 68 + wm + gid + 8];
            uint32_t a2 = As[(k + 4 + tig) * 68 + wm + gid];
            uint32_t a3 = As[(k + 4 + tig) * 68 + wm + gid + 8];
#pragma unroll
            for (int j = 0; j < 4; j++) {
                uint32_t b0 = Bs[(k + tig) * 68 + wn + j * 8 + gid];
                uint32_t b1 = Bs[(k + 4 + tig) * 68 + wn + j * 8 + gid];
                mma_tf32(acc[j][0], acc[j][1], acc[j][2], acc[j][3], a0, a1, a2, a3, b0, b1);
            }
        }
        __syncthreads();
    }
#pragma unroll
    for (int j = 0; j < 4; j++) {
        int n = n0 + wn + j * 8 + tig * 2;
        int m = m0 + wm + gid;
        float v0 = acc[j][0], v1 = acc[j][1], v2 = acc[j][2], v3 = acc[j][3];
        if (bias) { float b0 = bias[n], b1 = bias[n + 1]; v0 += b0; v1 += b1; v2 += b0; v3 += b1; }
        size_t o0 = (size_t)m * N + n, o1 = (size_t)(m + 8) * N + n;
        C[o0] = v0; C[o0 + 1] = v1; C[o1] = v2; C[o1 + 1] = v3;
    }
}

// ---------------- head GEMM 128x128 (reg-prefetch) ----------------
__global__ __launch_bounds__(256) void hg_kernel(const float* __restrict__ A,
                                                 const float* __restrict__ B,
                                                 float* __restrict__ C,
                                                 int M, int N, int K) {
    __shared__ uint32_t As[32 * 132];
    __shared__ uint32_t Bs[32 * 132];
    int tid = threadIdx.x, lane = tid & 31, wid = tid >> 5;
    int wm = (wid & 3) * 32, wn = (wid >> 2) * 64;
    int m0 = blockIdx.y * 128, n0 = blockIdx.x * 128;
    int gid = lane >> 2, tig = lane & 3;
    int row4 = tid >> 3, kq4 = (tid & 7) * 4;
    float4 aP[4], bP[4];
#pragma unroll
    for (int it = 0; it < 4; it++) {
        aP[it] = *(const float4*)&A[(size_t)(m0 + row4 + it * 32) * K + kq4];
        bP[it] = *(const float4*)&B[(size_t)(n0 + row4 + it * 32) * K + kq4];
    }
    float acc[2][8][4];
#pragma unroll
    for (int mb = 0; mb < 2; mb++)
#pragma unroll
        for (int j = 0; j < 8; j++)
#pragma unroll
            for (int i = 0; i < 4; i++) acc[mb][j][i] = 0.f;

    for (int k0 = 0; k0 < K; k0 += 32) {
#pragma unroll
        for (int it = 0; it < 4; it++) {
            int row = row4 + it * 32;
            As[(kq4 + 0) * 132 + row] = f2tf32(aP[it].x);
            As[(kq4 + 1) * 132 + row] = f2tf32(aP[it].y);
            As[(kq4 + 2) * 132 + row] = f2tf32(aP[it].z);
            As[(kq4 + 3) * 132 + row] = f2tf32(aP[it].w);
            Bs[(kq4 + 0) * 132 + row] = f2tf32(bP[it].x);
            Bs[(kq4 + 1) * 132 + row] = f2tf32(bP[it].y);
            Bs[(kq4 + 2) * 132 + row] = f2tf32(bP[it].z);
            Bs[(kq4 + 3) * 132 + row] = f2tf32(bP[it].w);
        }
        __syncthreads();
        if (k0 + 32 < K) {
#pragma unroll
            for (int it = 0; it < 4; it++) {
                aP[it] = *(const float4*)&A[(size_t)(m0 + row4 + it * 32) * K + k0 + 32 + kq4];
                bP[it] = *(const float4*)&B[(size_t)(n0 + row4 + it * 32) * K + k0 + 32 + kq4];
            }
        }
#pragma unroll
        for (int s = 0; s < 4; s++) {
            int k = s * 8;
            uint32_t a[2][4];
#pragma unroll
            for (int mb = 0; mb < 2; mb++) {
                int mo = wm + mb * 16;
                a[mb][0] = As[(k + tig) * 132 + mo + gid];
                a[mb][1] = As[(k + tig) * 132 + mo + gid + 8];
                a[mb][2] = As[(k + 4 + tig) * 132 + mo + gid];
                a[mb][3] = As[(k + 4 + tig) * 132 + mo + gid + 8];
            }
#pragma unroll
            for (int j = 0; j < 8; j++) {
                uint32_t b0 = Bs[(k + tig) * 132 + wn + j * 8 + gid];
                uint32_t b1 = Bs[(k + 4 + tig) * 132 + wn + j * 8 + gid];
#pragma unroll
                for (int mb = 0; mb < 2; mb++)
                    mma_tf32(acc[mb][j][0], acc[mb][j][1], acc[mb][j][2], acc[mb][j][3],
                             a[mb][0], a[mb][1], a[mb][2], a[mb][3], b0, b1);
            }
        }
        __syncthreads();
    }
#pragma unroll
    for (int mb = 0; mb < 2; mb++)
#pragma unroll
        for (int j = 0; j < 8; j++) {
            int n = n0 + wn + j * 8 + tig * 2;
            int m = m0 + wm + mb * 16 + gid;
            size_t o0 = (size_t)m * N + n, o1 = (size_t)(m + 8) * N + n;
            C[o0] = acc[mb][j][0]; C[o0 + 1] = acc[mb][j][1];
            C[o1] = acc[mb][j][2]; C[o1 + 1] = acc[mb][j][3];
        }
}

// ---------------- flash attention (tf32): qtile=16, 256 threads ----------------
#define FA_SMEM ((16 * 520 + 64 * 68 + 16 * 68) * 4)
__global__ __launch_bounds__(256) void fattn_kernel(const float* __restrict__ q,
                                                    const float* __restrict__ k,
                                                    const float* __restrict__ v,
                                                    float* __restrict__ ctx) {
    extern __shared__ float sm[];
    float*    Ps  = sm;
    uint32_t* Ks  = (uint32_t*)(sm + 16 * 520);
    float*    Qs  = sm + 16 * 520 + 64 * 68;
    int qt = blockIdx.x;
    int bh = blockIdx.y;
    int b = bh >> 2, h = bh & 3;
    int tid = threadIdx.x, w = tid >> 5, lane = tid & 31;
    int gid = lane >> 2, tig = lane & 3;
    int q0 = qt * 16;
    int ktmax = (q0 + 79) / 64;

    {
        int row = tid >> 4, dq = (tid & 15) * 4;
        float4 t4 = *(const float4*)&q[(size_t)(b * SEQ + q0 + row) * 256 + h * 64 + dq];
        Qs[row * 68 + dq] = t4.x; Qs[row * 68 + dq + 1] = t4.y;
        Qs[row * 68 + dq + 2] = t4.z; Qs[row * 68 + dq + 3] = t4.w;
    }
    __syncthreads();
    uint32_t qa[8][4];
#pragma unroll
    for (int kb = 0; kb < 8; kb++) {
        qa[kb][0] = f2tf32(Qs[gid * 68 + kb * 8 + tig]);
        qa[kb][1] = f2tf32(Qs[(gid + 8) * 68 + kb * 8 + tig]);
        qa[kb][2] = f2tf32(Qs[gid * 68 + kb * 8 + tig + 4]);
        qa[kb][3] = f2tf32(Qs[(gid + 8) * 68 + kb * 8 + tig + 4]);
    }
    for (int kt = 0; kt < ktmax; kt++) {
        __syncthreads();
        for (int u = tid; u < 1024; u += 256) {
            int row = u >> 4, dq = (u & 15) * 4;
            float4 t4 = *(const float4*)&k[(size_t)(b * SEQ + kt * 64 + row) * 256 + h * 64 + dq];
            Ks[row * 68 + dq] = f2tf32(t4.x); Ks[row * 68 + dq + 1] = f2tf32(t4.y);
            Ks[row * 68 + dq + 2] = f2tf32(t4.z); Ks[row * 68 + dq + 3] = f2tf32(t4.w);
        }
        __syncthreads();
        float c0 = 0.f, c1 = 0.f, c2 = 0.f, c3 = 0.f;
#pragma unroll
        for (int kb = 0; kb < 8; kb++) {
            uint32_t b0 = Ks[(w * 8 + gid) * 68 + kb * 8 + tig];
            uint32_t b1 = Ks[(w * 8 + gid) * 68 + kb * 8 + tig + 4];
            mma_tf32(c0, c1, c2, c3, qa[kb][0], qa[kb][1], qa[kb][2], qa[kb][3], b0, b1);
        }
        int qg0 = q0 + gid, qg1 = qg0 + 8;
        int kg = kt * 64 + w * 8 + 2 * tig;
        Ps[gid * 520 + kg]           = (kg     <= qg0) ? c0 * 0.125f : -1e30f;
        Ps[gid * 520 + kg + 1]       = (kg + 1 <= qg0) ? c1 * 0.125f : -1e30f;
        Ps[(gid + 8) * 520 + kg]     = (kg     <= qg1) ? c2 * 0.125f : -1e30f;
        Ps[(gid + 8) * 520 + kg + 1] = (kg + 1 <= qg1) ? c3 * 0.125f : -1e30f;
    }
    __syncthreads();
    {
        int row = tid >> 4;
        int c0i = tid & 15;
        int ncols = ktmax * 64;
        float m = -1e30f;
        for (int c = c0i; c < ncols; c += 16) m = fmaxf(m, Ps[row * 520 + c]);
        m = fmaxf(m, __shfl_xor_sync(0xffffffffu, m, 1));
        m = fmaxf(m, __shfl_xor_sync(0xffffffffu, m, 2));
        m = fmaxf(m, __shfl_xor_sync(0xffffffffu, m, 4));
        m = fmaxf(m, __shfl_xor_sync(0xffffffffu, m, 8));
        float s = 0.f;
        for (int c = c0i; c < ncols; c += 16) {
            float e = expf(Ps[row * 520 + c] - m);
            Ps[row * 520 + c] = e;
            s += e;
        }
        s += __shfl_xor_sync(0xffffffffu, s, 1);
        s += __shfl_xor_sync(0xffffffffu, s, 2);
        s += __shfl_xor_sync(0xffffffffu, s, 4);
        s += __shfl_xor_sync(0xffffffffu, s, 8);
        float inv = 1.f / s;
        for (int c = c0i; c < ncols; c += 16)
            Ps[row * 520 + c] = __uint_as_float(f2tf32(Ps[row * 520 + c] * inv));
    }
    __syncthreads();
    uint32_t* Pu = (uint32_t*)Ps;
    float o0 = 0.f, o1 = 0.f, o2 = 0.f, o3 = 0.f;
    for (int kt = 0; kt < ktmax; kt++) {
        for (int u = tid; u < 1024; u += 256) {
            int row = u >> 4, dq = (u & 15) * 4;
            float4 t4 = *(const float4*)&v[(size_t)(b * SEQ + kt * 64 + row) * 256 + h * 64 + dq];
            Ks[row * 68 + dq] = f2tf32(t4.x); Ks[row * 68 + dq + 1] = f2tf32(t4.y);
            Ks[row * 68 + dq + 2] = f2tf32(t4.z); Ks[row * 68 + dq + 3] = f2tf32(t4.w);
        }
        __syncthreads();
#pragma unroll
        for (int kb = 0; kb < 8; kb++) {
            uint32_t a0 = Pu[gid * 520 + kt * 64 + kb * 8 + tig];
            uint32_t a1 = Pu[(gid + 8) * 520 + kt * 64 + kb * 8 + tig];
            uint32_t a2 = Pu[gid * 520 + kt * 64 + kb * 8 + tig + 4];
            uint32_t a3 = Pu[(gid + 8) * 520 + kt * 64 + kb * 8 + tig + 4];
            uint32_t b0 = Ks[(kb * 8 + tig) * 68 + w * 8 + gid];
            uint32_t b1 = Ks[(kb * 8 + 4 + tig) * 68 + w * 8 + gid];
            mma_tf32(o0, o1, o2, o3, a0, a1, a2, a3, b0, b1);
        }
        __syncthreads();
    }
    {
        int n = h * 64 + w * 8 + 2 * tig;
        size_t mrow = (size_t)(b * SEQ + q0 + gid);
        ctx[mrow * 256 + n] = o0;
        ctx[mrow * 256 + n + 1] = o1;
        ctx[(mrow + 8) * 256 + n] = o2;
        ctx[(mrow + 8) * 256 + n + 1] = o3;
    }
}

// ---------------- upfront: recipe softmax + neuron embeddings ----------------
__global__ void rsoft_all_kernel(const float* __restrict__ recipes, const float* __restrict__ basis,
                                 float* __restrict__ Rsoft_all, float* __restrict__ nemb_all) {
    int l = blockIdx.x;
    const float* rec = recipes + l * (NNEUR * NBASIS);
    float* Rsoft = Rsoft_all + l * (NNEUR * NBASIS);
    float* nemb  = nemb_all + l * (NNEUR * D_MODEL);
    int tid = threadIdx.x;
    __shared__ float rs[NNEUR * NBASIS];
    if (tid < NNEUR) {
        float row[NBASIS];
        float mx = -1e30f;
        for (int nb = 0; nb < NBASIS; nb++) { row[nb] = rec[tid * NBASIS + nb]; mx = fmaxf(mx, row[nb]); }
        float s = 0.f;
        for (int nb = 0; nb < NBASIS; nb++) { row[nb] = expf(row[nb] - mx); s += row[nb]; }
        float invs = 1.f / s;
        for (int nb = 0; nb < NBASIS; nb++) {
            float vv = row[nb] * invs;
            rs[tid * NBASIS + nb] = vv;
            Rsoft[tid * NBASIS + nb] = vv;
        }
    }
    __syncthreads();
    for (int i = tid; i < NNEUR * D_MODEL; i += 256) {
        int n = i >> 8, d = i & 255;
        float s = 0.f;
        for (int nb = 0; nb < NBASIS; nb++) s = fmaf(rs[n * NBASIS + nb], basis[nb * 256 + d], s);
        nemb[i] = s;
    }
}

// ---------------- upfront: neuron cores as tensor-core GEMM ----------------
// NC[64, esize] = Rsoft[64, 32] @ src[32, esize], fp16 output.
// grid: (256, 4*NLAYER); blockIdx.y -> (l, arr); guard n0 < esize.
__global__ __launch_bounds__(256) void ncore_gemm_kernel(
        const float* __restrict__ Rsoft_all,
        const float* __restrict__ A1, const float* __restrict__ A2,
        const float* __restrict__ B1, const float* __restrict__ B2,
        __half* __restrict__ NA1_all, __half* __restrict__ NA2_all,
        __half* __restrict__ NB1_all, __half* __restrict__ NB2_all) {
    int l = blockIdx.y >> 2, arr = blockIdx.y & 3;
    const float* src; __half* dst; int esize;
    if (arr == 0)      { src = A1; dst = NA1_all + l * NA_SZ; esize = 8192; }
    else if (arr == 1) { src = A2; dst = NA2_all + l * NA_SZ; esize = 8192; }
    else if (arr == 2) { src = B1; dst = NB1_all + l * NB_SZ; esize = 16384; }
    else               { src = B2; dst = NB2_all + l * NB_SZ; esize = 16384; }
    int n0 = blockIdx.x * 64;
    if (n0 >= esize) return;
    const float* Rs = Rsoft_all + l * (NNEUR * NBASIS);

    __shared__ uint32_t As[32 * 68];   // [k][m]
    __shared__ uint32_t Bs[32 * 68];   // [k][n]
    int tid = threadIdx.x, lane = tid & 31, wid = tid >> 5;
    int wm = (wid & 3) * 16, wn = (wid >> 2) * 32;
    int gid = lane >> 2, tig = lane & 3;

    // load A = Rsoft [64][32] (2048 elems, 8 per thread)
    for (int i = tid; i < 2048; i += 256) {
        int m = i >> 5, k = i & 31;
        As[k * 68 + m] = f2tf32(Rs[m * NBASIS + k]);
    }
    // load B = src [32][n0..n0+64) (2048 elems)
    for (int i = tid; i < 2048; i += 256) {
        int k = i >> 6, n = i & 63;
        Bs[k * 68 + n] = f2tf32(src[(size_t)k * esize + n0 + n]);
    }
    __syncthreads();
    float acc[4][4];
#pragma unroll
    for (int j = 0; j < 4; j++)
#pragma unroll
        for (int i = 0; i < 4; i++) acc[j][i] = 0.f;
#pragma unroll
    for (int s = 0; s < 4; s++) {
        int k = s * 8;
        uint32_t a0 = As[(k + tig) * 68 + wm + gid];
        uint32_t a1 = As[(k + tig) * 68 + wm + gid + 8];
        uint32_t a2 = As[(k + 4 + tig) * 68 + wm + gid];
        uint32_t a3 = As[(k + 4 + tig) * 68 + wm + gid + 8];
#pragma unroll
        for (int j = 0; j < 4; j++) {
            uint32_t b0 = Bs[(k + tig) * 68 + wn + j * 8 + gid];
            uint32_t b1 = Bs[(k + 4 + tig) * 68 + wn + j * 8 + gid];
            mma_tf32(acc[j][0], acc[j][1], acc[j][2], acc[j][3], a0, a1, a2, a3, b0, b1);
        }
    }
#pragma unroll
    for (int j = 0; j < 4; j++) {
        int n = n0 + wn + j * 8 + tig * 2;
        int m = wm + gid;
        *(__half2*)&dst[(size_t)m * esize + n] = __floats2half2_rn(acc[j][0], acc[j][1]);
        *(__half2*)&dst[(size_t)(m + 8) * esize + n] = __floats2half2_rn(acc[j][2], acc[j][3]);
    }
}

// ---------------- fused score + router (parallel warp top-k) ----------------
__global__ void scorerouter_kernel(const float* __restrict__ query, const float* __restrict__ nemb,
                                   int* __restrict__ topi, float* __restrict__ topw) {
    int t = blockIdx.x;
    int tid = threadIdx.x, warp = tid >> 5, lane = tid & 31;
    __shared__ float qrow[256];
    __shared__ float sc[NNEUR];
    __shared__ int   idxs[TOPK];
    __shared__ float wv[TOPK];
    qrow[tid] = query[t * 256 + tid];
    __syncthreads();
#pragma unroll
    for (int u = 0; u < 8; u++) {
        int n = warp * 8 + u;
        const float* nr = nemb + n * 256;
        float acc = 0.f;
#pragma unroll
        for (int i = 0; i < 8; i++) acc = fmaf(qrow[lane + 32 * i], nr[lane + 32 * i], acc);
#pragma unroll
        for (int o = 16; o; o >>= 1) acc += __shfl_down_sync(0xffffffffu, acc, o);
        if (!lane) sc[n] = acc;
    }
    __syncthreads();
    if (warp == 0) {
        float vals[TOPK];
#pragma unroll
        for (int kk = 0; kk < TOPK; kk++) {
            float v0 = sc[lane], v1 = sc[lane + 32];
            int i0 = lane, i1 = lane + 32;
            if (v1 > v0) { v0 = v1; i0 = i1; }
#pragma unroll
            for (int o = 16; o; o >>= 1) {
                float ov = __shfl_down_sync(0xffffffffu, v0, o);
                int oi = __shfl_down_sync(0xffffffffu, i0, o);
                if (ov > v0) { v0 = ov; i0 = oi; }
            }
            v0 = __shfl_sync(0xffffffffu, v0, 0);
            i0 = __shfl_sync(0xffffffffu, i0, 0);
            vals[kk] = v0;
            if (lane == 0) { idxs[kk] = i0; sc[i0] = -1e30f; }
            __syncwarp();
        }
        if (lane == 0) {
            float mx = vals[0];
            float e[TOPK], s = 0.f;
#pragma unroll
            for (int kk = 0; kk < TOPK; kk++) { e[kk] = expf(vals[kk] - mx); s += e[kk]; }
            float invs = 1.f / s;
#pragma unroll
            for (int kk = 0; kk < TOPK; kk++) wv[kk] = e[kk] * invs;
        }
    }
    __syncthreads();
    if (tid < TOPK) {
        topi[t * TOPK + tid] = idxs[tid];
        topw[t * TOPK + tid] = wv[tid];
    }
}

// ---------------- TT FFN stage A ----------------
struct SmemA {
    float N1[NNEUR * 128];
    float N2[NNEUR * 128];
    float xf_t[TPB_A][256];
    float a1[16][128];
    float a2t[16][128];
    float tt[16][128];
};

__global__ __launch_bounds__(512) void stageA_kernel(
        const float* __restrict__ xin, const float* __restrict__ n2g, const float* __restrict__ n2b,
        const int* __restrict__ topi, const float* __restrict__ topw,
        const __half* __restrict__ NA1, const __half* __restrict__ NA2,
        float* __restrict__ hpart) {
    extern __shared__ float smemraw[];
    SmemA& S = *reinterpret_cast<SmemA*>(smemraw);
    int tid = threadIdx.x, tg = tid >> 5, lane = tid & 31;
    int t0 = blockIdx.x * TPB_A;
    int r0 = blockIdx.y * RPER_A;
#pragma unroll
    for (int tok = 0; tok < 2; tok++) {
        int t = t0 + tg * 2 + tok;
        float vals[8];
        float s = 0.f, s2 = 0.f;
#pragma unroll
        for (int qd = 0; qd < 8; qd++) {
            float v = xin[t * 256 + lane + 32 * qd];
            vals[qd] = v; s += v; s2 = fmaf(v, v, s2);
        }
#pragma unroll
        for (int o = 16; o; o >>= 1) {
            s += __shfl_xor_sync(0xffffffffu, s, o);
            s2 += __shfl_xor_sync(0xffffffffu, s2, o);
        }
        float mean = s * (1.f / 256.f);
        float var = s2 * (1.f / 256.f) - mean * mean;
        float inv = rsqrtf(var + 1e-5f);
#pragma unroll
        for (int qd = 0; qd < 8; qd++) {
            int d = lane + 32 * qd;
            float nv = (vals[qd] - mean) * inv * n2g[d] + n2b[d];
            S.xf_t[tg * 2 + tok][(d & 15) * 16 + (d >> 4)] = nv;
        }
    }
    int nid[2][TOPK]; float nw[2][TOPK];
#pragma unroll
    for (int tok = 0; tok < 2; tok++) {
        int t = t0 + tg * 2 + tok;
#pragma unroll
        for (int kk = 0; kk < TOPK; kk++) { nid[tok][kk] = topi[t * TOPK + kk]; nw[tok][kk] = topw[t * TOPK + kk]; }
    }
    float hacc[2][2] = {{0.f, 0.f}, {0.f, 0.f}};
    int o = lane * 4;
    int jrow = lane >> 1;
    int kk0 = (lane & 1) * 4;
    int kq2 = lane >> 2;
    int l0 = (lane * 2) & 7, l1 = (lane * 2 + 1) & 7;

    for (int ri = 0; ri < RPER_A; ri++) {
        int r = r0 + ri;
        __syncthreads();
#pragma unroll
        for (int it = 0; it < 2; it++) {
            int u = tid + it * 512;
            int n = u >> 4, rest = u & 15;
            uint4 p1 = *(const uint4*)&NA1[(size_t)n * 8192 + rest * 512 + r * 8];
            h8_to_f8(p1, &S.N1[n * 128 + rest * 8]);
            uint4 p2 = *(const uint4*)&NA2[(size_t)n * 8192 + r * 128 + rest * 8];
            h8_to_f8(p2, &S.N2[n * 128 + rest * 8]);
        }
        __syncthreads();
#pragma unroll
        for (int tok = 0; tok < 2; tok++) {
            int xrow = tg * 2 + tok;
            float4 m1 = make_float4(0.f, 0.f, 0.f, 0.f);
            float4 m2 = make_float4(0.f, 0.f, 0.f, 0.f);
#pragma unroll
            for (int kk = 0; kk < TOPK; kk++) {
                float ww = nw[tok][kk];
                float4 s1 = *(const float4*)&S.N1[nid[tok][kk] * 128 + o];
                float4 s2 = *(const float4*)&S.N2[nid[tok][kk] * 128 + o];
                m1.x = fmaf(ww, s1.x, m1.x); m1.y = fmaf(ww, s1.y, m1.y);
                m1.z = fmaf(ww, s1.z, m1.z); m1.w = fmaf(ww, s1.w, m1.w);
                m2.x = fmaf(ww, s2.x, m2.x); m2.y = fmaf(ww, s2.y, m2.y);
                m2.z = fmaf(ww, s2.z, m2.z); m2.w = fmaf(ww, s2.w, m2.w);
            }
            *(float4*)&S.a1[tg][o] = m1;
            {
                int j = o >> 3, l = o & 7;
                S.a2t[tg][(l + 0) * 16 + j] = m2.x;
                S.a2t[tg][(l + 1) * 16 + j] = m2.y;
                S.a2t[tg][(l + 2) * 16 + j] = m2.z;
                S.a2t[tg][(l + 3) * 16 + j] = m2.w;
            }
            __syncwarp();
            {
                float t0r = 0.f, t1r = 0.f, t2r = 0.f, t3r = 0.f;
#pragma unroll
                for (int i = 0; i < 16; i++) {
                    float xv = S.xf_t[xrow][jrow * 16 + i];
                    float4 av = *(const float4*)&S.a1[tg][i * 8 + kk0];
                    t0r = fmaf(xv, av.x, t0r); t1r = fmaf(xv, av.y, t1r);
                    t2r = fmaf(xv, av.z, t2r); t3r = fmaf(xv, av.w, t3r);
                }
                S.tt[tg][(kk0 + 0) * 16 + jrow] = t0r;
                S.tt[tg][(kk0 + 1) * 16 + jrow] = t1r;
                S.tt[tg][(kk0 + 2) * 16 + jrow] = t2r;
                S.tt[tg][(kk0 + 3) * 16 + jrow] = t3r;
            }
            __syncwarp();
            {
                float s0 = 0.f, s1 = 0.f;
#pragma unroll
                for (int j4 = 0; j4 < 4; j4++) {
                    float4 tv = *(const float4*)&S.tt[tg][kq2 * 16 + j4 * 4];
                    float4 a0 = *(const float4*)&S.a2t[tg][l0 * 16 + j4 * 4];
                    float4 a1v = *(const float4*)&S.a2t[tg][l1 * 16 + j4 * 4];
                    s0 = fmaf(tv.x, a0.x, s0); s0 = fmaf(tv.y, a0.y, s0);
                    s0 = fmaf(tv.z, a0.z, s0); s0 = fmaf(tv.w, a0.w, s0);
                    s1 = fmaf(tv.x, a1v.x, s1); s1 = fmaf(tv.y, a1v.y, s1);
                    s1 = fmaf(tv.z, a1v.z, s1); s1 = fmaf(tv.w, a1v.w, s1);
                }
                hacc[tok][0] += s0;
                hacc[tok][1] += s1;
            }
            __syncwarp();
        }
    }
#pragma unroll
    for (int tok = 0; tok < 2; tok++) {
        int t = t0 + tg * 2 + tok;
        hpart[(blockIdx.y * T_TOK + t) * 64 + lane * 2]     = hacc[tok][0];
        hpart[(blockIdx.y * T_TOK + t) * 64 + lane * 2 + 1] = hacc[tok][1];
    }
}

// ---------------- TT FFN stage B ----------------
#define TRS 12
struct SmemB {
    float N1[NNEUR * 256];
    float N2[NNEUR * 256];
    float trT[16][32 * TRS];
    float hfT[TPB_B][64];
};

__global__ __launch_bounds__(512) void stageB_kernel(
        const float* __restrict__ hpart, const int* __restrict__ topi, const float* __restrict__ topw,
        const __half* __restrict__ NB1, const __half* __restrict__ NB2,
        float* __restrict__ ffnpart) {
    extern __shared__ float smemraw[];
    SmemB& S = *reinterpret_cast<SmemB*>(smemraw);
    int tid = threadIdx.x, tg = tid >> 5, lane = tid & 31;
    int t0 = blockIdx.x * TPB_B;
    int r0 = blockIdx.y * RPER_B;
    for (int u = tid; u < TPB_B * 64; u += 512) {
        float s = 0.f;
#pragma unroll
        for (int g = 0; g < RG_A; g++) s += hpart[g * (T_TOK * 64) + t0 * 64 + u];
        int tok = u >> 6, e = u & 63;
        S.hfT[tok][(e & 7) * 8 + (e >> 3)] = s;
    }
    __syncthreads();
    int nid[2][TOPK]; float nw[2][TOPK];
#pragma unroll
    for (int tok = 0; tok < 2; tok++) {
        int t = t0 + tg * 2 + tok;
#pragma unroll
        for (int kk = 0; kk < TOPK; kk++) { nid[tok][kk] = topi[t * TOPK + kk]; nw[tok][kk] = topw[t * TOPK + kk]; }
    }
    float oreg[2][32];
#pragma unroll
    for (int tok = 0; tok < 2; tok++)
#pragma unroll
        for (int i = 0; i < 32; i++) oreg[tok][i] = 0.f;

    for (int ri = 0; ri < RPER_B; ri++) {
        int r = r0 + ri;
        __syncthreads();
#pragma unroll
        for (int it = 0; it < 8; it++) {
            int u = tid + it * 512;
            if (u < 2048) {
                int n = u >> 5, rest = u & 31;
                int i = rest >> 2, kq = (rest & 3) * 8;
                uint4 p = *(const uint4*)&NB1[(size_t)n * 16384 + i * 2048 + r * 32 + kq];
                h8_to_f8(p, &S.N1[n * 256 + i * 32 + kq]);
            } else {
                int u2 = u - 2048;
                int n = u2 >> 5, c = (u2 & 31) * 8;
                uint4 p = *(const uint4*)&NB2[(size_t)n * 16384 + r * 256 + c];
                h8_to_f8(p, &S.N2[n * 256 + c]);
            }
        }
        __syncthreads();
#pragma unroll
        for (int tok = 0; tok < 2; tok++) {
            int xrow = tg * 2 + tok;
            float b1r[8], b2r[8];
#pragma unroll
            for (int i = 0; i < 8; i++) {
                float s1 = 0.f, s2 = 0.f;
#pragma unroll
                for (int kk = 0; kk < TOPK; kk++) {
                    s1 = fmaf(nw[tok][kk], S.N1[nid[tok][kk] * 256 + i * 32 + lane], s1);
                    s2 = fmaf(nw[tok][kk], S.N2[nid[tok][kk] * 256 + i * 32 + lane], s2);
                }
                b1r[i] = s1; b2r[i] = s2;
            }
#pragma unroll
            for (int j2 = 0; j2 < 4; j2++) {
                float4 h0 = *(const float4*)&S.hfT[xrow][(j2 * 2) * 8];
                float4 h1 = *(const float4*)&S.hfT[xrow][(j2 * 2) * 8 + 4];
                float sA = h0.x * b1r[0] + h0.y * b1r[1] + h0.z * b1r[2] + h0.w * b1r[3]
                         + h1.x * b1r[4] + h1.y * b1r[5] + h1.z * b1r[6] + h1.w * b1r[7];
                float4 g0 = *(const float4*)&S.hfT[xrow][(j2 * 2 + 1) * 8];
                float4 g1 = *(const float4*)&S.hfT[xrow][(j2 * 2 + 1) * 8 + 4];
                float sB = g0.x * b1r[0] + g0.y * b1r[1] + g0.z * b1r[2] + g0.w * b1r[3]
                         + g1.x * b1r[4] + g1.y * b1r[5] + g1.z * b1r[6] + g1.w * b1r[7];
                *(float2*)&S.trT[tg][lane * TRS + j2 * 2] = make_float2(sA, sB);
            }
            __syncwarp();
#pragma unroll
            for (int kk = 0; kk < 32; kk++) {
                float4 t0v = *(const float4*)&S.trT[tg][kk * TRS];
                float4 t1v = *(const float4*)&S.trT[tg][kk * TRS + 4];
                float s = t0v.x * b2r[0] + t0v.y * b2r[1] + t0v.z * b2r[2] + t0v.w * b2r[3]
                        + t1v.x * b2r[4] + t1v.y * b2r[5] + t1v.z * b2r[6] + t1v.w * b2r[7];
                oreg[tok][kk] += s;
            }
            __syncwarp();
        }
    }
#pragma unroll
    for (int tok = 0; tok < 2; tok++) {
        int t = t0 + tg * 2 + tok;
        float* dst = ffnpart + (blockIdx.y * T_TOK + t) * (size_t)DFF;
#pragma unroll
        for (int kk = 0; kk < 32; kk++) dst[kk * 32 + lane] = oreg[tok][kk];
    }
}

__global__ void gelu_reduce_kernel(const float* __restrict__ ffnpart, float* __restrict__ ffn) {
    int idx = blockIdx.x * 256 + threadIdx.x;
    float4 s = ((const float4*)ffnpart)[idx];
#pragma unroll
    for (int g = 1; g < RG_B; g++) {
        float4 p = ((const float4*)(ffnpart + (size_t)g * (T_TOK * DFF)))[idx];
        s.x += p.x; s.y += p.y; s.z += p.z; s.w += p.w;
    }
    float4 r;
    r.x = 0.5f * s.x * (1.f + erff(s.x * 0.70710678118654752f));
    r.y = 0.5f * s.y * (1.f + erff(s.y * 0.70710678118654752f));
    r.z = 0.5f * s.z * (1.f + erff(s.z * 0.70710678118654752f));
    r.w = 0.5f * s.w * (1.f + erff(s.w * 0.70710678118654752f));
    ((float4*)ffn)[idx] = r;
}

// ---------------- host orchestration ----------------
extern "C" void kernel_launch(void* const* d_in, const int* in_sizes, int n_in,
                              void* d_out, int out_size) {
    const int*   ids    = (const int*)d_in[0];
    const float* te     = (const float*)d_in[1];
    const float* pe     = (const float*)d_in[2];
    const float* qW     = (const float*)d_in[3];
    const float* qb     = (const float*)d_in[4];
    const float* kW     = (const float*)d_in[5];
    const float* kb     = (const float*)d_in[6];
    const float* vW     = (const float*)d_in[7];
    const float* vb     = (const float*)d_in[8];
    const float* sW     = (const float*)d_in[9];
    const float* sb     = (const float*)d_in[10];
    const float* recipes= (const float*)d_in[11];
    const float* wdW    = (const float*)d_in[12];
    const float* wdb    = (const float*)d_in[13];
    const float* n1g    = (const float*)d_in[14];
    const float* n1b    = (const float*)d_in[15];
    const float* n2g    = (const float*)d_in[16];
    const float* n2b    = (const float*)d_in[17];
    const float* basis  = (const float*)d_in[18];
    const float* A1     = (const float*)d_in[19];
    const float* A2     = (const float*)d_in[20];
    const float* B1     = (const float*)d_in[21];
    const float* B2     = (const float*)d_in[22];
    const float* fng    = (const float*)d_in[23];
    const float* fnb    = (const float*)d_in[24];
    float* out = (float*)d_out;

    float *x, *nrm1, *q, *k, *v, *ctx, *query, *ffn, *Rsoft, *nemb, *hpart, *ffnpart, *wdpart;
    float *topw;
    __half *NA1, *NA2, *NB1, *NB2;
    int* topi;
    uint32_t *qW32, *kW32, *vW32, *sW32, *wdW32;
    cudaGetSymbolAddress((void**)&x, g_x);
    cudaGetSymbolAddress((void**)&nrm1, g_nrm1);
    cudaGetSymbolAddress((void**)&q, g_q);
    cudaGetSymbolAddress((void**)&k, g_k);
    cudaGetSymbolAddress((void**)&v, g_v);
    cudaGetSymbolAddress((void**)&ctx, g_ctx);
    cudaGetSymbolAddress((void**)&query, g_query);
    cudaGetSymbolAddress((void**)&ffn, g_ffn);
    cudaGetSymbolAddress((void**)&Rsoft, g_Rsoft);
    cudaGetSymbolAddress((void**)&nemb, g_nemb);
    cudaGetSymbolAddress((void**)&hpart, g_hpart);
    cudaGetSymbolAddress((void**)&ffnpart, g_ffnpart);
    cudaGetSymbolAddress((void**)&wdpart, g_wdpart);
    cudaGetSymbolAddress((void**)&NA1, g_NA1);
    cudaGetSymbolAddress((void**)&NA2, g_NA2);
    cudaGetSymbolAddress((void**)&NB1, g_NB1);
    cudaGetSymbolAddress((void**)&NB2, g_NB2);
    cudaGetSymbolAddress((void**)&topi, g_topi);
    cudaGetSymbolAddress((void**)&topw, g_topw);
    cudaGetSymbolAddress((void**)&qW32, g_qW32);
    cudaGetSymbolAddress((void**)&kW32, g_kW32);
    cudaGetSymbolAddress((void**)&vW32, g_vW32);
    cudaGetSymbolAddress((void**)&sW32, g_sW32);
    cudaGetSymbolAddress((void**)&wdW32, g_wdW32);

    cudaFuncSetAttribute(stageA_kernel, cudaFuncAttributeMaxDynamicSharedMemorySize, (int)sizeof(SmemA));
    cudaFuncSetAttribute(stageB_kernel, cudaFuncAttributeMaxDynamicSharedMemorySize, (int)sizeof(SmemB));
    cudaFuncSetAttribute(fattn_kernel, cudaFuncAttributeMaxDynamicSharedMemorySize, FA_SMEM);

    // upfront
    embed_kernel<<<T_TOK, 256>>>(ids, te, pe, x);
    Cvt5 cj;
    cj.src[0] = qW;  cj.dst[0] = qW32;  cj.n[0] = NLAYER * 65536;
    cj.src[1] = kW;  cj.dst[1] = kW32;  cj.n[1] = NLAYER * 65536;
    cj.src[2] = vW;  cj.dst[2] = vW32;  cj.n[2] = NLAYER * 65536;
    cj.src[3] = sW;  cj.dst[3] = sW32;  cj.n[3] = NLAYER * 131072;
    cj.src[4] = wdW; cj.dst[4] = wdW32; cj.n[4] = NLAYER * 262144;
    cvt5_kernel<<<dim3(NLAYER * 262144 / 256, 5), 256>>>(cj);
    rsoft_all_kernel<<<NLAYER, 256>>>(recipes, basis, Rsoft, nemb);
    ncore_gemm_kernel<<<dim3(256, 4 * NLAYER), 256>>>(Rsoft, A1, A2, B1, B2, NA1, NA2, NB1, NB2);

    for (int l = 0; l < NLAYER; l++) {
        ln_kernel<<<T_TOK / 8, 256>>>(x, n1g + l * 256, n1b + l * 256, nrm1);
        W4u gb;
        gb.W[0] = qW32 + l * 65536;  gb.bias[0] = qb + l * 256; gb.out[0] = q;
        gb.W[1] = kW32 + l * 65536;  gb.bias[1] = kb + l * 256; gb.out[1] = k;
        gb.W[2] = vW32 + l * 65536;  gb.bias[2] = vb + l * 256; gb.out[2] = v;
        gb.W[3] = sW32 + l * 131072; gb.bias[3] = nullptr;      gb.out[3] = query;
        tc_gemmb<<<dim3(4, 16, 4), 256>>>(nrm1, gb, 1024, 256, 256);
        fattn_kernel<<<dim3(SEQ / 16, 8), 256, FA_SMEM>>>(q, k, v, ctx);
        tc_gemm_sk<<<dim3(4, 16, 2), 256>>>(ctx, sW32 + l * 131072 + 65536, wdpart, 256, 256, 128);
        wdadd_kernel<<<T_TOK, 256>>>(wdpart, sb + l * 256, query);
        scorerouter_kernel<<<T_TOK, 256>>>(query, nemb + l * (NNEUR * D_MODEL), topi, topw);
        stageA_kernel<<<dim3(T_TOK / TPB_A, RG_A), 512, sizeof(SmemA)>>>(
            x, n2g + l * 256, n2b + l * 256, topi, topw, NA1 + l * NA_SZ, NA2 + l * NA_SZ, hpart);
        stageB_kernel<<<dim3(T_TOK / TPB_B, RG_B), 512, sizeof(SmemB)>>>(
            hpart, topi, topw, NB1 + l * NB_SZ, NB2 + l * NB_SZ, ffnpart);
        gelu_reduce_kernel<<<T_TOK * DFF / 1024, 256>>>(ffnpart, ffn);
        tc_gemm_sk<<<dim3(4, 16, 2), 256>>>(ffn, wdW32 + l * 262144, wdpart, 256, 1024, 512);
        wdadd_kernel<<<T_TOK, 256>>>(wdpart, wdb + l * 256, x);
    }
    ln_kernel<<<T_TOK / 8, 256>>>(x, fng, fnb, nrm1);
    hg_kernel<<<dim3(VOCAB / 128, T_TOK / 128), 256>>>(nrm1, te, out, 1024, VOCAB, 256);
}

// round 17
// speedup vs baseline: 1.0407x; 1.0395x over previous
#include <cuda_runtime.h>
#include <cuda_bf16.h>
#include <cuda_fp16.h>
#include <math.h>
#include <stdint.h>

// ---------------- constants ----------------
#define T_TOK   1024
#define D_MODEL 256
#define SEQ     512
#define NHEAD   4
#define DHEAD   64
#define NBASIS  32
#define RRANK   64
#define NNEUR   64
#define TOPK    8
#define DFF     1024
#define NLAYER  4
#define VOCAB   32000
#define TPB_A   32
#define RG_A    8
#define RPER_A  (RRANK / RG_A)
#define TPB_B   32
#define RG_B    8
#define RPER_B  (RRANK / RG_B)
#define NA_SZ   (NNEUR * 8192)
#define NB_SZ   (NNEUR * 16384)

// ---------------- scratch ----------------
__device__ float g_x[T_TOK * D_MODEL];
__device__ float g_nrm1[T_TOK * D_MODEL];
__device__ float g_q[T_TOK * D_MODEL];
__device__ float g_k[T_TOK * D_MODEL];
__device__ float g_v[T_TOK * D_MODEL];
__device__ float g_ctx[T_TOK * D_MODEL];
__device__ float g_query[T_TOK * D_MODEL];
__device__ float g_ffn[T_TOK * DFF];
__device__ float g_Rsoft[NLAYER * NNEUR * NBASIS];
__device__ float g_nemb[NLAYER * NNEUR * D_MODEL];
__device__ float g_hpart[RG_A * T_TOK * 64];
__device__ float g_ffnpart[RG_B * T_TOK * DFF];
__device__ float g_wdpart[2 * T_TOK * D_MODEL];
__device__ int   g_topi[T_TOK * TOPK];
__device__ float g_topw[T_TOK * TOPK];
__device__ __half g_NA1[NLAYER * NA_SZ];
__device__ __half g_NA2[NLAYER * NA_SZ];
__device__ __half g_NB1[NLAYER * NB_SZ];
__device__ __half g_NB2[NLAYER * NB_SZ];
__device__ uint32_t g_qW32[NLAYER * 65536];
__device__ uint32_t g_kW32[NLAYER * 65536];
__device__ uint32_t g_vW32[NLAYER * 65536];
__device__ uint32_t g_sW32[NLAYER * 131072];
__device__ uint32_t g_wdW32[NLAYER * 262144];

// ---------------- tf32 helpers ----------------
__device__ __forceinline__ uint32_t f2tf32(float f) {
    uint32_t u;
    asm("cvt.rna.tf32.f32 %0, %1;" : "=r"(u) : "f"(f));
    return u;
}
__device__ __forceinline__ void mma_tf32(float& c0, float& c1, float& c2, float& c3,
                                         uint32_t a0, uint32_t a1, uint32_t a2, uint32_t a3,
                                         uint32_t b0, uint32_t b1) {
    asm("mma.sync.aligned.m16n8k8.row.col.f32.tf32.tf32.f32 "
        "{%0,%1,%2,%3},{%4,%5,%6,%7},{%8,%9},{%0,%1,%2,%3};"
        : "+f"(c0), "+f"(c1), "+f"(c2), "+f"(c3)
        : "r"(a0), "r"(a1), "r"(a2), "r"(a3), "r"(b0), "r"(b1));
}

// ---------------- merged upfront conversion ----------------
struct Cvt5 { const float* src[5]; uint32_t* dst[5]; int n[5]; };
__global__ void cvt5_kernel(Cvt5 j) {
    int a = blockIdx.y;
    int i = blockIdx.x * 256 + threadIdx.x;
    if (i < j.n[a]) j.dst[a][i] = f2tf32(j.src[a][i]);
}

// ---------------- embed ----------------
__global__ void embed_kernel(const int* __restrict__ ids, const float* __restrict__ te,
                             const float* __restrict__ pe, float* __restrict__ x) {
    int t = blockIdx.x, d = threadIdx.x;
    int s = t & (SEQ - 1);
    x[t * 256 + d] = te[ids[t] * 256 + d] + pe[s * 256 + d];
}

// ---------------- layernorm: warp per token ----------------
__global__ void ln_kernel(const float* __restrict__ x, const float* __restrict__ g,
                          const float* __restrict__ b, float* __restrict__ out) {
    int warp = threadIdx.x >> 5, lane = threadIdx.x & 31;
    int t = blockIdx.x * 8 + warp;
    float vals[8];
    float s = 0.f, s2 = 0.f;
#pragma unroll
    for (int qd = 0; qd < 8; qd++) {
        float v = x[t * 256 + lane + 32 * qd];
        vals[qd] = v; s += v; s2 = fmaf(v, v, s2);
    }
#pragma unroll
    for (int o = 16; o; o >>= 1) {
        s += __shfl_xor_sync(0xffffffffu, s, o);
        s2 += __shfl_xor_sync(0xffffffffu, s2, o);
    }
    float mean = s * (1.f / 256.f);
    float var = s2 * (1.f / 256.f) - mean * mean;
    float inv = rsqrtf(var + 1e-5f);
#pragma unroll
    for (int qd = 0; qd < 8; qd++) {
        int d = lane + 32 * qd;
        out[t * 256 + d] = (vals[qd] - mean) * inv * g[d] + b[d];
    }
}

// ---------------- split-K tf32 GEMM (reg-prefetch), partial out ----------------
__global__ __launch_bounds__(256) void tc_gemm_sk(const float* __restrict__ A,
                                                  const uint32_t* __restrict__ B,
                                                  float* __restrict__ Cpart,
                                                  int N, int K, int klen) {
    __shared__ uint32_t As[32 * 68];
    __shared__ uint32_t Bs[32 * 68];
    int tid = threadIdx.x, lane = tid & 31, wid = tid >> 5;
    int wm = (wid & 3) * 16, wn = (wid >> 2) * 32;
    int m0 = blockIdx.y * 64, n0 = blockIdx.x * 64;
    int gid = lane >> 2, tig = lane & 3;
    int kbeg = blockIdx.z * klen;
    float* C = Cpart + (size_t)blockIdx.z * T_TOK * D_MODEL;
    int arow[2], akq[2], bkb[2], bnq[2];
#pragma unroll
    for (int it = 0; it < 2; it++) {
        int u = tid + it * 256;
        arow[it] = u >> 3; akq[it] = (u & 7) * 4;
        bkb[it] = u >> 4; bnq[it] = (u & 15) * 4;
    }
    float4 aP[2]; uint4 bP[2];
#pragma unroll
    for (int it = 0; it < 2; it++) {
        aP[it] = *(const float4*)&A[(size_t)(m0 + arow[it]) * K + kbeg + akq[it]];
        bP[it] = *(const uint4*)&B[(size_t)(kbeg + bkb[it]) * N + n0 + bnq[it]];
    }
    float acc[4][4];
#pragma unroll
    for (int j = 0; j < 4; j++)
#pragma unroll
        for (int i = 0; i < 4; i++) acc[j][i] = 0.f;

    for (int k0 = kbeg; k0 < kbeg + klen; k0 += 32) {
#pragma unroll
        for (int it = 0; it < 2; it++) {
            As[(akq[it] + 0) * 68 + arow[it]] = f2tf32(aP[it].x);
            As[(akq[it] + 1) * 68 + arow[it]] = f2tf32(aP[it].y);
            As[(akq[it] + 2) * 68 + arow[it]] = f2tf32(aP[it].z);
            As[(akq[it] + 3) * 68 + arow[it]] = f2tf32(aP[it].w);
            *(uint4*)&Bs[bkb[it] * 68 + bnq[it]] = bP[it];
        }
        __syncthreads();
        if (k0 + 32 < kbeg + klen) {
#pragma unroll
            for (int it = 0; it < 2; it++) {
                aP[it] = *(const float4*)&A[(size_t)(m0 + arow[it]) * K + k0 + 32 + akq[it]];
                bP[it] = *(const uint4*)&B[(size_t)(k0 + 32 + bkb[it]) * N + n0 + bnq[it]];
            }
        }
#pragma unroll
        for (int s = 0; s < 4; s++) {
            int k = s * 8;
            uint32_t a0 = As[(k + tig) * 68 + wm + gid];
            uint32_t a1 = As[(k + tig) * 68 + wm + gid + 8];
            uint32_t a2 = As[(k + 4 + tig) * 68 + wm + gid];
            uint32_t a3 = As[(k + 4 + tig) * 68 + wm + gid + 8];
#pragma unroll
            for (int j = 0; j < 4; j++) {
                uint32_t b0 = Bs[(k + tig) * 68 + wn + j * 8 + gid];
                uint32_t b1 = Bs[(k + 4 + tig) * 68 + wn + j * 8 + gid];
                mma_tf32(acc[j][0], acc[j][1], acc[j][2], acc[j][3], a0, a1, a2, a3, b0, b1);
            }
        }
        __syncthreads();
    }
#pragma unroll
    for (int j = 0; j < 4; j++) {
        int n = n0 + wn + j * 8 + tig * 2;
        int m = m0 + wm + gid;
        size_t o0 = (size_t)m * N + n, o1 = (size_t)(m + 8) * N + n;
        C[o0] = acc[j][0]; C[o0 + 1] = acc[j][1]; C[o1] = acc[j][2]; C[o1 + 1] = acc[j][3];
    }
}

// combine: x += p0 + p1 + bias
__global__ void wdadd_kernel(const float* __restrict__ p, const float* __restrict__ bias,
                             float* __restrict__ x) {
    int idx = blockIdx.x * 256 + threadIdx.x;
    x[idx] += p[idx] + p[T_TOK * D_MODEL + idx] + bias[idx & 255];
}

// ---------------- batched tf32 GEMM (reg-prefetch, 4 weights) ----------------
struct W4u { const uint32_t* W[4]; const float* bias[4]; float* out[4]; };

__global__ __launch_bounds__(256) void tc_gemmb(const float* __restrict__ A, W4u gb,
                                                int M, int N, int K) {
    const uint32_t* __restrict__ B = gb.W[blockIdx.z];
    const float* __restrict__ bias = gb.bias[blockIdx.z];
    float* __restrict__ C = gb.out[blockIdx.z];
    __shared__ uint32_t As[32 * 68];
    __shared__ uint32_t Bs[32 * 68];
    int tid = threadIdx.x, lane = tid & 31, wid = tid >> 5;
    int wm = (wid & 3) * 16, wn = (wid >> 2) * 32;
    int m0 = blockIdx.y * 64, n0 = blockIdx.x * 64;
    int gid = lane >> 2, tig = lane & 3;
    int arow[2], akq[2], bkb[2], bnq[2];
#pragma unroll
    for (int it = 0; it < 2; it++) {
        int u = tid + it * 256;
        arow[it] = u >> 3; akq[it] = (u & 7) * 4;
        bkb[it] = u >> 4; bnq[it] = (u & 15) * 4;
    }
    float4 aP[2]; uint4 bP[2];
#pragma unroll
    for (int it = 0; it < 2; it++) {
        aP[it] = *(const float4*)&A[(size_t)(m0 + arow[it]) * K + akq[it]];
        bP[it] = *(const uint4*)&B[(size_t)bkb[it] * N + n0 + bnq[it]];
    }
    float acc[4][4];
#pragma unroll
    for (int j = 0; j < 4; j++)
#pragma unroll
        for (int i = 0; i < 4; i++) acc[j][i] = 0.f;

    for (int k0 = 0; k0 < K; k0 += 32) {
#pragma unroll
        for (int it = 0; it < 2; it++) {
            As[(akq[it] + 0) * 68 + arow[it]] = f2tf32(aP[it].x);
            As[(akq[it] + 1) * 68 + arow[it]] = f2tf32(aP[it].y);
            As[(akq[it] + 2) * 68 + arow[it]] = f2tf32(aP[it].z);
            As[(akq[it] + 3) * 68 + arow[it]] = f2tf32(aP[it].w);
            *(uint4*)&Bs[bkb[it] * 68 + bnq[it]] = bP[it];
        }
        __syncthreads();
        if (k0 + 32 < K) {
#pragma unroll
            for (int it = 0; it < 2; it++) {
                aP[it] = *(const float4*)&A[(size_t)(m0 + arow[it]) * K + k0 + 32 + akq[it]];
                bP[it] = *(const uint4*)&B[(size_t)(k0 + 32 + bkb[it]) * N + n0 + bnq[it]];
            }
        }
#pragma unroll
        for (int s = 0; s < 4; s++) {
            int k = s * 8;
            uint32_t a0 = As[(k + tig) * 68 + wm + gid];
            uint32_t a1 = As[(k + tig) * 68 + wm + gid + 8];
            uint32_t a2 = As[(k + 4 + tig) * 68 + wm + gid];
            uint32_t a3 = As[(k + 4 + tig) * 68 + wm + gid + 8];
#pragma unroll
            for (int j = 0; j < 4; j++) {
                uint32_t b0 = Bs[(k + tig) * 68 + wn + j * 8 + gid];
                uint32_t b1 = Bs[(k + 4 + tig) * 68 + wn + j * 8 + gid];
                mma_tf32(acc[j][0], acc[j][1], acc[j][2], acc[j][3], a0, a1, a2, a3, b0, b1);
            }
        }
        __syncthreads();
    }
#pragma unroll
    for (int j = 0; j < 4; j++) {
        int n = n0 + wn + j * 8 + tig * 2;
        int m = m0 + wm + gid;
        float v0 = acc[j][0], v1 = acc[j][1], v2 = acc[j][2], v3 = acc[j][3];
        if (bias) { float b0 = bias[n], b1 = bias[n + 1]; v0 += b0; v1 += b1; v2 += b0; v3 += b1; }
        size_t o0 = (size_t)m * N + n, o1 = (size_t)(m + 8) * N + n;
        C[o0] = v0; C[o0 + 1] = v1; C[o1] = v2; C[o1 + 1] = v3;
    }
}

// ---------------- head GEMM 128x128 (reg-prefetch) ----------------
__global__ __launch_bounds__(256) void hg_kernel(const float* __restrict__ A,
                                                 const float* __restrict__ B,
                                                 float* __restrict__ C,
                                                 int M, int N, int K) {
    __shared__ uint32_t As[32 * 132];
    __shared__ uint32_t Bs[32 * 132];
    int tid = threadIdx.x, lane = tid & 31, wid = tid >> 5;
    int wm = (wid & 3) * 32, wn = (wid >> 2) * 64;
    int m0 = blockIdx.y * 128, n0 = blockIdx.x * 128;
    int gid = lane >> 2, tig = lane & 3;
    int row4 = tid >> 3, kq4 = (tid & 7) * 4;
    float4 aP[4], bP[4];
#pragma unroll
    for (int it = 0; it < 4; it++) {
        aP[it] = *(const float4*)&A[(size_t)(m0 + row4 + it * 32) * K + kq4];
        bP[it] = *(const float4*)&B[(size_t)(n0 + row4 + it * 32) * K + kq4];
    }
    float acc[2][8][4];
#pragma unroll
    for (int mb = 0; mb < 2; mb++)
#pragma unroll
        for (int j = 0; j < 8; j++)
#pragma unroll
            for (int i = 0; i < 4; i++) acc[mb][j][i] = 0.f;

    for (int k0 = 0; k0 < K; k0 += 32) {
#pragma unroll
        for (int it = 0; it < 4; it++) {
            int row = row4 + it * 32;
            As[(kq4 + 0) * 132 + row] = f2tf32(aP[it].x);
            As[(kq4 + 1) * 132 + row] = f2tf32(aP[it].y);
            As[(kq4 + 2) * 132 + row] = f2tf32(aP[it].z);
            As[(kq4 + 3) * 132 + row] = f2tf32(aP[it].w);
            Bs[(kq4 + 0) * 132 + row] = f2tf32(bP[it].x);
            Bs[(kq4 + 1) * 132 + row] = f2tf32(bP[it].y);
            Bs[(kq4 + 2) * 132 + row] = f2tf32(bP[it].z);
            Bs[(kq4 + 3) * 132 + row] = f2tf32(bP[it].w);
        }
        __syncthreads();
        if (k0 + 32 < K) {
#pragma unroll
            for (int it = 0; it < 4; it++) {
                aP[it] = *(const float4*)&A[(size_t)(m0 + row4 + it * 32) * K + k0 + 32 + kq4];
                bP[it] = *(const float4*)&B[(size_t)(n0 + row4 + it * 32) * K + k0 + 32 + kq4];
            }
        }
#pragma unroll
        for (int s = 0; s < 4; s++) {
            int k = s * 8;
            uint32_t a[2][4];
#pragma unroll
            for (int mb = 0; mb < 2; mb++) {
                int mo = wm + mb * 16;
                a[mb][0] = As[(k + tig) * 132 + mo + gid];
                a[mb][1] = As[(k + tig) * 132 + mo + gid + 8];
                a[mb][2] = As[(k + 4 + tig) * 132 + mo + gid];
                a[mb][3] = As[(k + 4 + tig) * 132 + mo + gid + 8];
            }
#pragma unroll
            for (int j = 0; j < 8; j++) {
                uint32_t b0 = Bs[(k + tig) * 132 + wn + j * 8 + gid];
                uint32_t b1 = Bs[(k + 4 + tig) * 132 + wn + j * 8 + gid];
#pragma unroll
                for (int mb = 0; mb < 2; mb++)
                    mma_tf32(acc[mb][j][0], acc[mb][j][1], acc[mb][j][2], acc[mb][j][3],
                             a[mb][0], a[mb][1], a[mb][2], a[mb][3], b0, b1);
            }
        }
        __syncthreads();
    }
#pragma unroll
    for (int mb = 0; mb < 2; mb++)
#pragma unroll
        for (int j = 0; j < 8; j++) {
            int n = n0 + wn + j * 8 + tig * 2;
            int m = m0 + wm + mb * 16 + gid;
            size_t o0 = (size_t)m * N + n, o1 = (size_t)(m + 8) * N + n;
            C[o0] = acc[mb][j][0]; C[o0 + 1] = acc[mb][j][1];
            C[o1] = acc[mb][j][2]; C[o1 + 1] = acc[mb][j][3];
        }
}

// ---------------- flash attention (tf32): qtile=16, 256 threads ----------------
#define FA_SMEM ((16 * 520 + 64 * 68 + 16 * 68) * 4)
__global__ __launch_bounds__(256) void fattn_kernel(const float* __restrict__ q,
                                                    const float* __restrict__ k,
                                                    const float* __restrict__ v,
                                                    float* __restrict__ ctx) {
    extern __shared__ float sm[];
    float*    Ps  = sm;
    uint32_t* Ks  = (uint32_t*)(sm + 16 * 520);
    float*    Qs  = sm + 16 * 520 + 64 * 68;
    int qt = blockIdx.x;
    int bh = blockIdx.y;
    int b = bh >> 2, h = bh & 3;
    int tid = threadIdx.x, w = tid >> 5, lane = tid & 31;
    int gid = lane >> 2, tig = lane & 3;
    int q0 = qt * 16;
    int ktmax = (q0 + 79) / 64;

    {
        int row = tid >> 4, dq = (tid & 15) * 4;
        float4 t4 = *(const float4*)&q[(size_t)(b * SEQ + q0 + row) * 256 + h * 64 + dq];
        Qs[row * 68 + dq] = t4.x; Qs[row * 68 + dq + 1] = t4.y;
        Qs[row * 68 + dq + 2] = t4.z; Qs[row * 68 + dq + 3] = t4.w;
    }
    __syncthreads();
    uint32_t qa[8][4];
#pragma unroll
    for (int kb = 0; kb < 8; kb++) {
        qa[kb][0] = f2tf32(Qs[gid * 68 + kb * 8 + tig]);
        qa[kb][1] = f2tf32(Qs[(gid + 8) * 68 + kb * 8 + tig]);
        qa[kb][2] = f2tf32(Qs[gid * 68 + kb * 8 + tig + 4]);
        qa[kb][3] = f2tf32(Qs[(gid + 8) * 68 + kb * 8 + tig + 4]);
    }
    for (int kt = 0; kt < ktmax; kt++) {
        __syncthreads();
        for (int u = tid; u < 1024; u += 256) {
            int row = u >> 4, dq = (u & 15) * 4;
            float4 t4 = *(const float4*)&k[(size_t)(b * SEQ + kt * 64 + row) * 256 + h * 64 + dq];
            Ks[row * 68 + dq] = f2tf32(t4.x); Ks[row * 68 + dq + 1] = f2tf32(t4.y);
            Ks[row * 68 + dq + 2] = f2tf32(t4.z); Ks[row * 68 + dq + 3] = f2tf32(t4.w);
        }
        __syncthreads();
        float c0 = 0.f, c1 = 0.f, c2 = 0.f, c3 = 0.f;
#pragma unroll
        for (int kb = 0; kb < 8; kb++) {
            uint32_t b0 = Ks[(w * 8 + gid) * 68 + kb * 8 + tig];
            uint32_t b1 = Ks[(w * 8 + gid) * 68 + kb * 8 + tig + 4];
            mma_tf32(c0, c1, c2, c3, qa[kb][0], qa[kb][1], qa[kb][2], qa[kb][3], b0, b1);
        }
        int qg0 = q0 + gid, qg1 = qg0 + 8;
        int kg = kt * 64 + w * 8 + 2 * tig;
        Ps[gid * 520 + kg]           = (kg     <= qg0) ? c0 * 0.125f : -1e30f;
        Ps[gid * 520 + kg + 1]       = (kg + 1 <= qg0) ? c1 * 0.125f : -1e30f;
        Ps[(gid + 8) * 520 + kg]     = (kg     <= qg1) ? c2 * 0.125f : -1e30f;
        Ps[(gid + 8) * 520 + kg + 1] = (kg + 1 <= qg1) ? c3 * 0.125f : -1e30f;
    }
    __syncthreads();
    {
        int row = tid >> 4;
        int c0i = tid & 15;
        int ncols = ktmax * 64;
        float m = -1e30f;
        for (int c = c0i; c < ncols; c += 16) m = fmaxf(m, Ps[row * 520 + c]);
        m = fmaxf(m, __shfl_xor_sync(0xffffffffu, m, 1));
        m = fmaxf(m, __shfl_xor_sync(0xffffffffu, m, 2));
        m = fmaxf(m, __shfl_xor_sync(0xffffffffu, m, 4));
        m = fmaxf(m, __shfl_xor_sync(0xffffffffu, m, 8));
        float s = 0.f;
        for (int c = c0i; c < ncols; c += 16) {
            float e = expf(Ps[row * 520 + c] - m);
            Ps[row * 520 + c] = e;
            s += e;
        }
        s += __shfl_xor_sync(0xffffffffu, s, 1);
        s += __shfl_xor_sync(0xffffffffu, s, 2);
        s += __shfl_xor_sync(0xffffffffu, s, 4);
        s += __shfl_xor_sync(0xffffffffu, s, 8);
        float inv = 1.f / s;
        for (int c = c0i; c < ncols; c += 16)
            Ps[row * 520 + c] = __uint_as_float(f2tf32(Ps[row * 520 + c] * inv));
    }
    __syncthreads();
    uint32_t* Pu = (uint32_t*)Ps;
    float o0 = 0.f, o1 = 0.f, o2 = 0.f, o3 = 0.f;
    for (int kt = 0; kt < ktmax; kt++) {
        for (int u = tid; u < 1024; u += 256) {
            int row = u >> 4, dq = (u & 15) * 4;
            float4 t4 = *(const float4*)&v[(size_t)(b * SEQ + kt * 64 + row) * 256 + h * 64 + dq];
            Ks[row * 68 + dq] = f2tf32(t4.x); Ks[row * 68 + dq + 1] = f2tf32(t4.y);
            Ks[row * 68 + dq + 2] = f2tf32(t4.z); Ks[row * 68 + dq + 3] = f2tf32(t4.w);
        }
        __syncthreads();
#pragma unroll
        for (int kb = 0; kb < 8; kb++) {
            uint32_t a0 = Pu[gid * 520 + kt * 64 + kb * 8 + tig];
            uint32_t a1 = Pu[(gid + 8) * 520 + kt * 64 + kb * 8 + tig];
            uint32_t a2 = Pu[gid * 520 + kt * 64 + kb * 8 + tig + 4];
            uint32_t a3 = Pu[(gid + 8) * 520 + kt * 64 + kb * 8 + tig + 4];
            uint32_t b0 = Ks[(kb * 8 + tig) * 68 + w * 8 + gid];
            uint32_t b1 = Ks[(kb * 8 + 4 + tig) * 68 + w * 8 + gid];
            mma_tf32(o0, o1, o2, o3, a0, a1, a2, a3, b0, b1);
        }
        __syncthreads();
    }
    {
        int n = h * 64 + w * 8 + 2 * tig;
        size_t mrow = (size_t)(b * SEQ + q0 + gid);
        ctx[mrow * 256 + n] = o0;
        ctx[mrow * 256 + n + 1] = o1;
        ctx[(mrow + 8) * 256 + n] = o2;
        ctx[(mrow + 8) * 256 + n + 1] = o3;
    }
}

// ---------------- upfront: recipe softmax + neuron embeddings ----------------
__global__ void rsoft_all_kernel(const float* __restrict__ recipes, const float* __restrict__ basis,
                                 float* __restrict__ Rsoft_all, float* __restrict__ nemb_all) {
    int l = blockIdx.x;
    const float* rec = recipes + l * (NNEUR * NBASIS);
    float* Rsoft = Rsoft_all + l * (NNEUR * NBASIS);
    float* nemb  = nemb_all + l * (NNEUR * D_MODEL);
    int tid = threadIdx.x;
    __shared__ float rs[NNEUR * NBASIS];
    if (tid < NNEUR) {
        float row[NBASIS];
        float mx = -1e30f;
        for (int nb = 0; nb < NBASIS; nb++) { row[nb] = rec[tid * NBASIS + nb]; mx = fmaxf(mx, row[nb]); }
        float s = 0.f;
        for (int nb = 0; nb < NBASIS; nb++) { row[nb] = expf(row[nb] - mx); s += row[nb]; }
        float invs = 1.f / s;
        for (int nb = 0; nb < NBASIS; nb++) {
            float vv = row[nb] * invs;
            rs[tid * NBASIS + nb] = vv;
            Rsoft[tid * NBASIS + nb] = vv;
        }
    }
    __syncthreads();
    for (int i = tid; i < NNEUR * D_MODEL; i += 256) {
        int n = i >> 8, d = i & 255;
        float s = 0.f;
        for (int nb = 0; nb < NBASIS; nb++) s = fmaf(rs[n * NBASIS + nb], basis[nb * 256 + d], s);
        nemb[i] = s;
    }
}

// ---------------- upfront: neuron-core precompute (fp16 out, x2 blocking, float4 rs) ----------------
__global__ void ncore_all_kernel(const float* __restrict__ Rsoft_all,
                                 const float* __restrict__ A1, const float* __restrict__ A2,
                                 const float* __restrict__ B1, const float* __restrict__ B2,
                                 __half* __restrict__ NA1_all, __half* __restrict__ NA2_all,
                                 __half* __restrict__ NB1_all, __half* __restrict__ NB2_all) {
    int l = blockIdx.y >> 2, arr = blockIdx.y & 3;
    const float* src; __half* dst; int esize;
    if (arr == 0)      { src = A1; dst = NA1_all + l * NA_SZ; esize = 8192; }
    else if (arr == 1) { src = A2; dst = NA2_all + l * NA_SZ; esize = 8192; }
    else if (arr == 2) { src = B1; dst = NB1_all + l * NB_SZ; esize = 16384; }
    else               { src = B2; dst = NB2_all + l * NB_SZ; esize = 16384; }
    __shared__ __align__(16) float rs[NNEUR * NBASIS];
    int tid = threadIdx.x;
    for (int i = tid; i < NNEUR * NBASIS; i += 256) rs[i] = Rsoft_all[l * (NNEUR * NBASIS) + i];
    __syncthreads();
    int e2 = blockIdx.x * 256 + tid;
    if (e2 >= esize / 2) return;
    int e = e2 * 2;
    float2 v[NBASIS];
#pragma unroll
    for (int nb = 0; nb < NBASIS; nb++) v[nb] = *(const float2*)&src[nb * esize + e];
    for (int n = 0; n < NNEUR; n++) {
        const float4* rsr = (const float4*)&rs[n * NBASIS];
        float a0 = 0.f, a1 = 0.f;
#pragma unroll
        for (int q4 = 0; q4 < NBASIS / 4; q4++) {
            float4 r4 = rsr[q4];
            a0 = fmaf(r4.x, v[q4 * 4 + 0].x, a0); a1 = fmaf(r4.x, v[q4 * 4 + 0].y, a1);
            a0 = fmaf(r4.y, v[q4 * 4 + 1].x, a0); a1 = fmaf(r4.y, v[q4 * 4 + 1].y, a1);
            a0 = fmaf(r4.z, v[q4 * 4 + 2].x, a0); a1 = fmaf(r4.z, v[q4 * 4 + 2].y, a1);
            a0 = fmaf(r4.w, v[q4 * 4 + 3].x, a0); a1 = fmaf(r4.w, v[q4 * 4 + 3].y, a1);
        }
        *(__half2*)&dst[n * esize + e] = __floats2half2_rn(a0, a1);
    }
}

// ---------------- fused score + router (parallel warp top-k) ----------------
__global__ void scorerouter_kernel(const float* __restrict__ query, const float* __restrict__ nemb,
                                   int* __restrict__ topi, float* __restrict__ topw) {
    int t = blockIdx.x;
    int tid = threadIdx.x, warp = tid >> 5, lane = tid & 31;
    __shared__ float qrow[256];
    __shared__ float sc[NNEUR];
    __shared__ int   idxs[TOPK];
    __shared__ float wv[TOPK];
    qrow[tid] = query[t * 256 + tid];
    __syncthreads();
#pragma unroll
    for (int u = 0; u < 8; u++) {
        int n = warp * 8 + u;
        const float* nr = nemb + n * 256;
        float acc = 0.f;
#pragma unroll
        for (int i = 0; i < 8; i++) acc = fmaf(qrow[lane + 32 * i], nr[lane + 32 * i], acc);
#pragma unroll
        for (int o = 16; o; o >>= 1) acc += __shfl_down_sync(0xffffffffu, acc, o);
        if (!lane) sc[n] = acc;
    }
    __syncthreads();
    if (warp == 0) {
        float vals[TOPK];
#pragma unroll
        for (int kk = 0; kk < TOPK; kk++) {
            float v0 = sc[lane], v1 = sc[lane + 32];
            int i0 = lane, i1 = lane + 32;
            if (v1 > v0) { v0 = v1; i0 = i1; }
#pragma unroll
            for (int o = 16; o; o >>= 1) {
                float ov = __shfl_down_sync(0xffffffffu, v0, o);
                int oi = __shfl_down_sync(0xffffffffu, i0, o);
                if (ov > v0) { v0 = ov; i0 = oi; }
            }
            v0 = __shfl_sync(0xffffffffu, v0, 0);
            i0 = __shfl_sync(0xffffffffu, i0, 0);
            vals[kk] = v0;
            if (lane == 0) { idxs[kk] = i0; sc[i0] = -1e30f; }
            __syncwarp();
        }
        if (lane == 0) {
            float mx = vals[0];
            float e[TOPK], s = 0.f;
#pragma unroll
            for (int kk = 0; kk < TOPK; kk++) { e[kk] = expf(vals[kk] - mx); s += e[kk]; }
            float invs = 1.f / s;
#pragma unroll
            for (int kk = 0; kk < TOPK; kk++) wv[kk] = e[kk] * invs;
        }
    }
    __syncthreads();
    if (tid < TOPK) {
        topi[t * TOPK + tid] = idxs[tid];
        topw[t * TOPK + tid] = wv[tid];
    }
}

// ---------------- TT FFN stage A: fp16 smem slices (2 blocks/SM) ----------------
struct SmemA {
    __half N1h[NNEUR * 128];   // 16KB  [n][i*8+k]
    __half N2h[NNEUR * 128];   // 16KB  [n][chunk]
    float xf_t[TPB_A][256];    // 32KB
    float a1[16][128];         // 8KB
    float a2t[16][128];        // 8KB
    float tt[16][128];         // 8KB
};

__global__ __launch_bounds__(512) void stageA_kernel(
        const float* __restrict__ xin, const float* __restrict__ n2g, const float* __restrict__ n2b,
        const int* __restrict__ topi, const float* __restrict__ topw,
        const __half* __restrict__ NA1, const __half* __restrict__ NA2,
        float* __restrict__ hpart) {
    extern __shared__ float smemraw[];
    SmemA& S = *reinterpret_cast<SmemA*>(smemraw);
    int tid = threadIdx.x, tg = tid >> 5, lane = tid & 31;
    int t0 = blockIdx.x * TPB_A;
    int r0 = blockIdx.y * RPER_A;
#pragma unroll
    for (int tok = 0; tok < 2; tok++) {
        int t = t0 + tg * 2 + tok;
        float vals[8];
        float s = 0.f, s2 = 0.f;
#pragma unroll
        for (int qd = 0; qd < 8; qd++) {
            float v = xin[t * 256 + lane + 32 * qd];
            vals[qd] = v; s += v; s2 = fmaf(v, v, s2);
        }
#pragma unroll
        for (int o = 16; o; o >>= 1) {
            s += __shfl_xor_sync(0xffffffffu, s, o);
            s2 += __shfl_xor_sync(0xffffffffu, s2, o);
        }
        float mean = s * (1.f / 256.f);
        float var = s2 * (1.f / 256.f) - mean * mean;
        float inv = rsqrtf(var + 1e-5f);
#pragma unroll
        for (int qd = 0; qd < 8; qd++) {
            int d = lane + 32 * qd;
            float nv = (vals[qd] - mean) * inv * n2g[d] + n2b[d];
            S.xf_t[tg * 2 + tok][(d & 15) * 16 + (d >> 4)] = nv;
        }
    }
    int nid[2][TOPK]; float nw[2][TOPK];
#pragma unroll
    for (int tok = 0; tok < 2; tok++) {
        int t = t0 + tg * 2 + tok;
#pragma unroll
        for (int kk = 0; kk < TOPK; kk++) { nid[tok][kk] = topi[t * TOPK + kk]; nw[tok][kk] = topw[t * TOPK + kk]; }
    }
    float hacc[2][2] = {{0.f, 0.f}, {0.f, 0.f}};
    int o = lane * 4;
    int jrow = lane >> 1;
    int kk0 = (lane & 1) * 4;
    int kq2 = lane >> 2;
    int l0 = (lane * 2) & 7, l1 = (lane * 2 + 1) & 7;

    for (int ri = 0; ri < RPER_A; ri++) {
        int r = r0 + ri;
        __syncthreads();
        // raw fp16 copy of rank slices (1024 uint4 each)
#pragma unroll
        for (int it = 0; it < 2; it++) {
            int u = tid + it * 512;
            int n = u >> 4, rest = u & 15;
            *(uint4*)&S.N1h[n * 128 + rest * 8] =
                *(const uint4*)&NA1[(size_t)n * 8192 + rest * 512 + r * 8];
            *(uint4*)&S.N2h[n * 128 + rest * 8] =
                *(const uint4*)&NA2[(size_t)n * 8192 + r * 128 + rest * 8];
        }
        __syncthreads();
#pragma unroll
        for (int tok = 0; tok < 2; tok++) {
            int xrow = tg * 2 + tok;
            float4 m1 = make_float4(0.f, 0.f, 0.f, 0.f);
            float4 m2 = make_float4(0.f, 0.f, 0.f, 0.f);
#pragma unroll
            for (int kk = 0; kk < TOPK; kk++) {
                float ww = nw[tok][kk];
                uint2 p1 = *(const uint2*)&S.N1h[nid[tok][kk] * 128 + o];
                uint2 p2 = *(const uint2*)&S.N2h[nid[tok][kk] * 128 + o];
                const __half2* h1 = (const __half2*)&p1;
                const __half2* h2 = (const __half2*)&p2;
                float2 f10 = __half22float2(h1[0]), f11 = __half22float2(h1[1]);
                float2 f20 = __half22float2(h2[0]), f21 = __half22float2(h2[1]);
                m1.x = fmaf(ww, f10.x, m1.x); m1.y = fmaf(ww, f10.y, m1.y);
                m1.z = fmaf(ww, f11.x, m1.z); m1.w = fmaf(ww, f11.y, m1.w);
                m2.x = fmaf(ww, f20.x, m2.x); m2.y = fmaf(ww, f20.y, m2.y);
                m2.z = fmaf(ww, f21.x, m2.z); m2.w = fmaf(ww, f21.y, m2.w);
            }
            *(float4*)&S.a1[tg][o] = m1;
            {
                int j = o >> 3, l = o & 7;
                S.a2t[tg][(l + 0) * 16 + j] = m2.x;
                S.a2t[tg][(l + 1) * 16 + j] = m2.y;
                S.a2t[tg][(l + 2) * 16 + j] = m2.z;
                S.a2t[tg][(l + 3) * 16 + j] = m2.w;
            }
            __syncwarp();
            {
                float t0r = 0.f, t1r = 0.f, t2r = 0.f, t3r = 0.f;
#pragma unroll
                for (int i = 0; i < 16; i++) {
                    float xv = S.xf_t[xrow][jrow * 16 + i];
                    float4 av = *(const float4*)&S.a1[tg][i * 8 + kk0];
                    t0r = fmaf(xv, av.x, t0r); t1r = fmaf(xv, av.y, t1r);
                    t2r = fmaf(xv, av.z, t2r); t3r = fmaf(xv, av.w, t3r);
                }
                S.tt[tg][(kk0 + 0) * 16 + jrow] = t0r;
                S.tt[tg][(kk0 + 1) * 16 + jrow] = t1r;
                S.tt[tg][(kk0 + 2) * 16 + jrow] = t2r;
                S.tt[tg][(kk0 + 3) * 16 + jrow] = t3r;
            }
            __syncwarp();
            {
                float s0 = 0.f, s1 = 0.f;
#pragma unroll
                for (int j4 = 0; j4 < 4; j4++) {
                    float4 tv = *(const float4*)&S.tt[tg][kq2 * 16 + j4 * 4];
                    float4 a0 = *(const float4*)&S.a2t[tg][l0 * 16 + j4 * 4];
                    float4 a1v = *(const float4*)&S.a2t[tg][l1 * 16 + j4 * 4];
                    s0 = fmaf(tv.x, a0.x, s0); s0 = fmaf(tv.y, a0.y, s0);
                    s0 = fmaf(tv.z, a0.z, s0); s0 = fmaf(tv.w, a0.w, s0);
                    s1 = fmaf(tv.x, a1v.x, s1); s1 = fmaf(tv.y, a1v.y, s1);
                    s1 = fmaf(tv.z, a1v.z, s1); s1 = fmaf(tv.w, a1v.w, s1);
                }
                hacc[tok][0] += s0;
                hacc[tok][1] += s1;
            }
            __syncwarp();
        }
    }
#pragma unroll
    for (int tok = 0; tok < 2; tok++) {
        int t = t0 + tg * 2 + tok;
        hpart[(blockIdx.y * T_TOK + t) * 64 + lane * 2]     = hacc[tok][0];
        hpart[(blockIdx.y * T_TOK + t) * 64 + lane * 2 + 1] = hacc[tok][1];
    }
}

// ---------------- TT FFN stage B: fp16 smem slices, RG_B=8 (2 blocks/SM) ----------------
#define TRS 12
struct SmemB {
    __half N1h[NNEUR * 256];   // 32KB
    __half N2h[NNEUR * 256];   // 32KB
    float trT[16][32 * TRS];   // 24KB
    float hfT[TPB_B][64];      // 8KB
};

__global__ __launch_bounds__(512) void stageB_kernel(
        const float* __restrict__ hpart, const int* __restrict__ topi, const float* __restrict__ topw,
        const __half* __restrict__ NB1, const __half* __restrict__ NB2,
        float* __restrict__ ffnpart) {
    extern __shared__ float smemraw[];
    SmemB& S = *reinterpret_cast<SmemB*>(smemraw);
    int tid = threadIdx.x, tg = tid >> 5, lane = tid & 31;
    int t0 = blockIdx.x * TPB_B;
    int r0 = blockIdx.y * RPER_B;
    for (int u = tid; u < TPB_B * 64; u += 512) {
        float s = 0.f;
#pragma unroll
        for (int g = 0; g < RG_A; g++) s += hpart[g * (T_TOK * 64) + t0 * 64 + u];
        int tok = u >> 6, e = u & 63;
        S.hfT[tok][(e & 7) * 8 + (e >> 3)] = s;
    }
    __syncthreads();
    int nid[2][TOPK]; float nw[2][TOPK];
#pragma unroll
    for (int tok = 0; tok < 2; tok++) {
        int t = t0 + tg * 2 + tok;
#pragma unroll
        for (int kk = 0; kk < TOPK; kk++) { nid[tok][kk] = topi[t * TOPK + kk]; nw[tok][kk] = topw[t * TOPK + kk]; }
    }
    float oreg[2][32];
#pragma unroll
    for (int tok = 0; tok < 2; tok++)
#pragma unroll
        for (int i = 0; i < 32; i++) oreg[tok][i] = 0.f;

    for (int ri = 0; ri < RPER_B; ri++) {
        int r = r0 + ri;
        __syncthreads();
        // raw fp16 copy of rank slices (2048 uint4 each)
#pragma unroll
        for (int it = 0; it < 4; it++) {
            int u = tid + it * 512;
            int n = u >> 5, rest = u & 31;
            int i = rest >> 2, kq = (rest & 3) * 8;
            *(uint4*)&S.N1h[n * 256 + i * 32 + kq] =
                *(const uint4*)&NB1[(size_t)n * 16384 + i * 2048 + r * 32 + kq];
            *(uint4*)&S.N2h[n * 256 + rest * 8] =
                *(const uint4*)&NB2[(size_t)n * 16384 + r * 256 + rest * 8];
        }
        __syncthreads();
#pragma unroll
        for (int tok = 0; tok < 2; tok++) {
            int xrow = tg * 2 + tok;
            float b1r[8], b2r[8];
#pragma unroll
            for (int i = 0; i < 8; i++) {
                float s1 = 0.f, s2 = 0.f;
#pragma unroll
                for (int kk = 0; kk < TOPK; kk++) {
                    s1 = fmaf(nw[tok][kk], __half2float(S.N1h[nid[tok][kk] * 256 + i * 32 + lane]), s1);
                    s2 = fmaf(nw[tok][kk], __half2float(S.N2h[nid[tok][kk] * 256 + i * 32 + lane]), s2);
                }
                b1r[i] = s1; b2r[i] = s2;
            }
#pragma unroll
            for (int j2 = 0; j2 < 4; j2++) {
                float4 h0 = *(const float4*)&S.hfT[xrow][(j2 * 2) * 8];
                float4 h1 = *(const float4*)&S.hfT[xrow][(j2 * 2) * 8 + 4];
                float sA = h0.x * b1r[0] + h0.y * b1r[1] + h0.z * b1r[2] + h0.w * b1r[3]
                         + h1.x * b1r[4] + h1.y * b1r[5] + h1.z * b1r[6] + h1.w * b1r[7];
                float4 g0 = *(const float4*)&S.hfT[xrow][(j2 * 2 + 1) * 8];
                float4 g1 = *(const float4*)&S.hfT[xrow][(j2 * 2 + 1) * 8 + 4];
                float sB = g0.x * b1r[0] + g0.y * b1r[1] + g0.z * b1r[2] + g0.w * b1r[3]
                         + g1.x * b1r[4] + g1.y * b1r[5] + g1.z * b1r[6] + g1.w * b1r[7];
                *(float2*)&S.trT[tg][lane * TRS + j2 * 2] = make_float2(sA, sB);
            }
            __syncwarp();
#pragma unroll
            for (int kk = 0; kk < 32; kk++) {
                float4 t0v = *(const float4*)&S.trT[tg][kk * TRS];
                float4 t1v = *(const float4*)&S.trT[tg][kk * TRS + 4];
                float s = t0v.x * b2r[0] + t0v.y * b2r[1] + t0v.z * b2r[2] + t0v.w * b2r[3]
                        + t1v.x * b2r[4] + t1v.y * b2r[5] + t1v.z * b2r[6] + t1v.w * b2r[7];
                oreg[tok][kk] += s;
            }
            __syncwarp();
        }
    }
#pragma unroll
    for (int tok = 0; tok < 2; tok++) {
        int t = t0 + tg * 2 + tok;
        float* dst = ffnpart + ((size_t)blockIdx.y * T_TOK + t) * (size_t)DFF;
#pragma unroll
        for (int kk = 0; kk < 32; kk++) dst[kk * 32 + lane] = oreg[tok][kk];
    }
}

__global__ void gelu_reduce_kernel(const float* __restrict__ ffnpart, float* __restrict__ ffn) {
    int idx = blockIdx.x * 256 + threadIdx.x;
    float4 s = ((const float4*)ffnpart)[idx];
#pragma unroll
    for (int g = 1; g < RG_B; g++) {
        float4 p = ((const float4*)(ffnpart + (size_t)g * (T_TOK * DFF)))[idx];
        s.x += p.x; s.y += p.y; s.z += p.z; s.w += p.w;
    }
    float4 r;
    r.x = 0.5f * s.x * (1.f + erff(s.x * 0.70710678118654752f));
    r.y = 0.5f * s.y * (1.f + erff(s.y * 0.70710678118654752f));
    r.z = 0.5f * s.z * (1.f + erff(s.z * 0.70710678118654752f));
    r.w = 0.5f * s.w * (1.f + erff(s.w * 0.70710678118654752f));
    ((float4*)ffn)[idx] = r;
}

// ---------------- host orchestration ----------------
extern "C" void kernel_launch(void* const* d_in, const int* in_sizes, int n_in,
                              void* d_out, int out_size) {
    const int*   ids    = (const int*)d_in[0];
    const float* te     = (const float*)d_in[1];
    const float* pe     = (const float*)d_in[2];
    const float* qW     = (const float*)d_in[3];
    const float* qb     = (const float*)d_in[4];
    const float* kW     = (const float*)d_in[5];
    const float* kb     = (const float*)d_in[6];
    const float* vW     = (const float*)d_in[7];
    const float* vb     = (const float*)d_in[8];
    const float* sW     = (const float*)d_in[9];
    const float* sb     = (const float*)d_in[10];
    const float* recipes= (const float*)d_in[11];
    const float* wdW    = (const float*)d_in[12];
    const float* wdb    = (const float*)d_in[13];
    const float* n1g    = (const float*)d_in[14];
    const float* n1b    = (const float*)d_in[15];
    const float* n2g    = (const float*)d_in[16];
    const float* n2b    = (const float*)d_in[17];
    const float* basis  = (const float*)d_in[18];
    const float* A1     = (const float*)d_in[19];
    const float* A2     = (const float*)d_in[20];
    const float* B1     = (const float*)d_in[21];
    const float* B2     = (const float*)d_in[22];
    const float* fng    = (const float*)d_in[23];
    const float* fnb    = (const float*)d_in[24];
    float* out = (float*)d_out;

    float *x, *nrm1, *q, *k, *v, *ctx, *query, *ffn, *Rsoft, *nemb, *hpart, *ffnpart, *wdpart;
    float *topw;
    __half *NA1, *NA2, *NB1, *NB2;
    int* topi;
    uint32_t *qW32, *kW32, *vW32, *sW32, *wdW32;
    cudaGetSymbolAddress((void**)&x, g_x);
    cudaGetSymbolAddress((void**)&nrm1, g_nrm1);
    cudaGetSymbolAddress((void**)&q, g_q);
    cudaGetSymbolAddress((void**)&k, g_k);
    cudaGetSymbolAddress((void**)&v, g_v);
    cudaGetSymbolAddress((void**)&ctx, g_ctx);
    cudaGetSymbolAddress((void**)&query, g_query);
    cudaGetSymbolAddress((void**)&ffn, g_ffn);
    cudaGetSymbolAddress((void**)&Rsoft, g_Rsoft);
    cudaGetSymbolAddress((void**)&nemb, g_nemb);
    cudaGetSymbolAddress((void**)&hpart, g_hpart);
    cudaGetSymbolAddress((void**)&ffnpart, g_ffnpart);
    cudaGetSymbolAddress((void**)&wdpart, g_wdpart);
    cudaGetSymbolAddress((void**)&NA1, g_NA1);
    cudaGetSymbolAddress((void**)&NA2, g_NA2);
    cudaGetSymbolAddress((void**)&NB1, g_NB1);
    cudaGetSymbolAddress((void**)&NB2, g_NB2);
    cudaGetSymbolAddress((void**)&topi, g_topi);
    cudaGetSymbolAddress((void**)&topw, g_topw);
    cudaGetSymbolAddress((void**)&qW32, g_qW32);
    cudaGetSymbolAddress((void**)&kW32, g_kW32);
    cudaGetSymbolAddress((void**)&vW32, g_vW32);
    cudaGetSymbolAddress((void**)&sW32, g_sW32);
    cudaGetSymbolAddress((void**)&wdW32, g_wdW32);

    cudaFuncSetAttribute(stageA_kernel, cudaFuncAttributeMaxDynamicSharedMemorySize, (int)sizeof(SmemA));
    cudaFuncSetAttribute(stageB_kernel, cudaFuncAttributeMaxDynamicSharedMemorySize, (int)sizeof(SmemB));
    cudaFuncSetAttribute(fattn_kernel, cudaFuncAttributeMaxDynamicSharedMemorySize, FA_SMEM);

    // upfront
    embed_kernel<<<T_TOK, 256>>>(ids, te, pe, x);
    Cvt5 cj;
    cj.src[0] = qW;  cj.dst[0] = qW32;  cj.n[0] = NLAYER * 65536;
    cj.src[1] = kW;  cj.dst[1] = kW32;  cj.n[1] = NLAYER * 65536;
    cj.src[2] = vW;  cj.dst[2] = vW32;  cj.n[2] = NLAYER * 65536;
    cj.src[3] = sW;  cj.dst[3] = sW32;  cj.n[3] = NLAYER * 131072;
    cj.src[4] = wdW; cj.dst[4] = wdW32; cj.n[4] = NLAYER * 262144;
    cvt5_kernel<<<dim3(NLAYER * 262144 / 256, 5), 256>>>(cj);
    rsoft_all_kernel<<<NLAYER, 256>>>(recipes, basis, Rsoft, nemb);
    ncore_all_kernel<<<dim3(32, 4 * NLAYER), 256>>>(Rsoft, A1, A2, B1, B2, NA1, NA2, NB1, NB2);

    for (int l = 0; l < NLAYER; l++) {
        ln_kernel<<<T_TOK / 8, 256>>>(x, n1g + l * 256, n1b + l * 256, nrm1);
        W4u gb;
        gb.W[0] = qW32 + l * 65536;  gb.bias[0] = qb + l * 256; gb.out[0] = q;
        gb.W[1] = kW32 + l * 65536;  gb.bias[1] = kb + l * 256; gb.out[1] = k;
        gb.W[2] = vW32 + l * 65536;  gb.bias[2] = vb + l * 256; gb.out[2] = v;
        gb.W[3] = sW32 + l * 131072; gb.bias[3] = nullptr;      gb.out[3] = query;
        tc_gemmb<<<dim3(4, 16, 4), 256>>>(nrm1, gb, 1024, 256, 256);
        fattn_kernel<<<dim3(SEQ / 16, 8), 256, FA_SMEM>>>(q, k, v, ctx);
        tc_gemm_sk<<<dim3(4, 16, 2), 256>>>(ctx, sW32 + l * 131072 + 65536, wdpart, 256, 256, 128);
        wdadd_kernel<<<T_TOK, 256>>>(wdpart, sb + l * 256, query);
        scorerouter_kernel<<<T_TOK, 256>>>(query, nemb + l * (NNEUR * D_MODEL), topi, topw);
        stageA_kernel<<<dim3(T_TOK / TPB_A, RG_A), 512, sizeof(SmemA)>>>(
            x, n2g + l * 256, n2b + l * 256, topi, topw, NA1 + l * NA_SZ, NA2 + l * NA_SZ, hpart);
        stageB_kernel<<<dim3(T_TOK / TPB_B, RG_B), 512, sizeof(SmemB)>>>(
            hpart, topi, topw, NB1 + l * NB_SZ, NB2 + l * NB_SZ, ffnpart);
        gelu_reduce_kernel<<<T_TOK * DFF / 1024, 256>>>(ffnpart, ffn);
        tc_gemm_sk<<<dim3(4, 16, 2), 256>>>(ffn, wdW32 + l * 262144, wdpart, 256, 1024, 512);
        wdadd_kernel<<<T_TOK, 256>>>(wdpart, wdb + l * 256, x);
    }
    ln_kernel<<<T_TOK / 8, 256>>>(x, fng, fnb, nrm1);
    hg_kernel<<<dim3(VOCAB / 128, T_TOK / 128), 256>>>(nrm1, te, out, 1024, VOCAB, 256);
}